// round 9
// baseline (speedup 1.0000x reference)
#include <cuda_runtime.h>
#include <cuda_fp16.h>
#include <cstdint>

#define NN 100000
#define EE 1600000
#define GG 4096
#define HH 128
#define LL 4
#define NT 782                  // ceil(100000/128) row-tiles of 128
#define NPAD (NT * 128)         // 100096

// ---------------- device scratch (no allocations allowed) ----------------
__device__ int     g_deg[NN];
__device__ int     g_cursor[NN];
__device__ int     g_rowptr[NN + 1];
__device__ uint2   g_cw[EE];                 // (src idx, weight bits) fused
__device__ float   g_dis[NN];
__device__ float4  g_h[(size_t)NPAD * 32];   // N x 128 fp32 (padded, zero-init)
__device__ __half2 g_m[(size_t)NPAD * 64];   // N x 128 fp16 (padded)
__device__ float   g_gsum[GG];
__device__ float   g_gcnt[GG];
__device__ int     g_blocksums[128];
__device__ int     g_blockoffs[128];
// W in m16n8k16 fragment layout, fp16 hi/lo: [L][p][kc 8][nt 16][r 2][lane 32]
__device__ uint32_t g_Bfrag16[LL][2][8][16][2][32];

// ---------------- helpers ----------------
__device__ __forceinline__ float warp_sum(float v) {
#pragma unroll
    for (int o = 16; o; o >>= 1) v += __shfl_xor_sync(0xffffffffu, v, o);
    return v;
}
__device__ __forceinline__ void fma4(float4& acc, float a, const float4& w) {
    acc.x = fmaf(a, w.x, acc.x);
    acc.y = fmaf(a, w.y, acc.y);
    acc.z = fmaf(a, w.z, acc.z);
    acc.w = fmaf(a, w.w, acc.w);
}
__device__ __forceinline__ void fma_h8(float* acc, float w, uint4 u) {
    float2 f0 = __half22float2(*(__half2*)&u.x);
    float2 f1 = __half22float2(*(__half2*)&u.y);
    float2 f2 = __half22float2(*(__half2*)&u.z);
    float2 f3 = __half22float2(*(__half2*)&u.w);
    acc[0] = fmaf(w, f0.x, acc[0]);
    acc[1] = fmaf(w, f0.y, acc[1]);
    acc[2] = fmaf(w, f1.x, acc[2]);
    acc[3] = fmaf(w, f1.y, acc[3]);
    acc[4] = fmaf(w, f2.x, acc[4]);
    acc[5] = fmaf(w, f2.y, acc[5]);
    acc[6] = fmaf(w, f3.x, acc[6]);
    acc[7] = fmaf(w, f3.y, acc[7]);
}
// fp16 hi/lo split of a float2, packed as half2 words
__device__ __forceinline__ void split2(float2 v, uint32_t& hi, uint32_t& lo) {
    __half hx = __float2half_rn(v.x), hy = __float2half_rn(v.y);
    __half lx = __float2half_rn(v.x - __half2float(hx));
    __half ly = __float2half_rn(v.y - __half2float(hy));
    __half2 h2 = __halves2half2(hx, hy);
    __half2 l2 = __halves2half2(lx, ly);
    hi = *(uint32_t*)&h2;
    lo = *(uint32_t*)&l2;
}
__device__ __forceinline__ void mma_f16(float* d, uint32_t a0, uint32_t a1,
                                        uint32_t a2, uint32_t a3,
                                        uint32_t b0, uint32_t b1) {
    asm("mma.sync.aligned.m16n8k16.row.col.f32.f16.f16.f32 "
        "{%0,%1,%2,%3},{%4,%5,%6,%7},{%8,%9},{%0,%1,%2,%3};"
        : "+f"(d[0]), "+f"(d[1]), "+f"(d[2]), "+f"(d[3])
        : "r"(a0), "r"(a1), "r"(a2), "r"(a3), "r"(b0), "r"(b1));
}

// ---------------- setup kernels ----------------
__global__ void zero_kernel() {
    int i = blockIdx.x * blockDim.x + threadIdx.x;
    if (i < NN) { g_deg[i] = 0; g_cursor[i] = 0; }
    if (i < GG) { g_gsum[i] = 0.f; g_gcnt[i] = 0.f; }
}

__global__ void count_kernel(const int* __restrict__ dst) {
    int e = blockIdx.x * blockDim.x + threadIdx.x;
    if (e < EE) atomicAdd(&g_deg[dst[e]], 1);
}

__global__ void dis_kernel() {
    int i = blockIdx.x * blockDim.x + threadIdx.x;
    if (i < NN) g_dis[i] = rsqrtf((float)(g_deg[i] + 1));
}

__global__ void scan1_kernel() {
    __shared__ int sh[1024];
    int tid = threadIdx.x;
    int idx = blockIdx.x * 1024 + tid;
    int v = (idx < NN) ? g_deg[idx] : 0;
    sh[tid] = v;
    __syncthreads();
#pragma unroll
    for (int off = 1; off < 1024; off <<= 1) {
        int t = (tid >= off) ? sh[tid - off] : 0;
        __syncthreads();
        sh[tid] += t;
        __syncthreads();
    }
    if (idx < NN) g_rowptr[idx] = sh[tid] - v;
    if (tid == 1023) g_blocksums[blockIdx.x] = sh[1023];
}

__global__ void scan2_kernel(int nblocks) {
    __shared__ int sh[128];
    int tid = threadIdx.x;
    int v = (tid < nblocks) ? g_blocksums[tid] : 0;
    sh[tid] = v;
    __syncthreads();
#pragma unroll
    for (int off = 1; off < 128; off <<= 1) {
        int t = (tid >= off) ? sh[tid - off] : 0;
        __syncthreads();
        sh[tid] += t;
        __syncthreads();
    }
    if (tid < nblocks) g_blockoffs[tid] = sh[tid] - v;
    if (tid == 0) g_rowptr[NN] = EE;
}

__global__ void scan3_kernel() {
    int idx = blockIdx.x * 1024 + threadIdx.x;
    if (idx < NN) g_rowptr[idx] += g_blockoffs[blockIdx.x];
}

__global__ void fill_kernel(const int* __restrict__ src, const int* __restrict__ dst) {
    int e = blockIdx.x * blockDim.x + threadIdx.x;
    if (e >= EE) return;
    int s = src[e];
    int d = dst[e];
    int pos = g_rowptr[d] + atomicAdd(&g_cursor[d], 1);
    g_cw[pos] = make_uint2((unsigned)s, __float_as_uint(g_dis[s] * g_dis[d]));
}

// ---------------- W prep: fp16 hi/lo split into m16n8k16 fragment layout -------
__global__ void prep_kernel(const float* __restrict__ Wgnn) {
    int idx = blockIdx.x * 256 + threadIdx.x;
    if (idx >= LL * 8 * 16 * 2 * 32) return;
    int lane = idx & 31;
    int r    = (idx >> 5) & 1;
    int nt   = (idx >> 6) & 15;
    int kc   = (idx >> 10) & 7;
    int l    = idx >> 13;
    int t = lane & 3, g = lane >> 2;
    int k0 = kc * 16 + r * 8 + 2 * t;
    int n  = nt * 8 + g;
    float w0 = Wgnn[(size_t)l * 16384 + k0 * 128 + n];
    float w1 = Wgnn[(size_t)l * 16384 + (k0 + 1) * 128 + n];
    uint32_t hi, lo;
    split2(make_float2(w0, w1), hi, lo);
    g_Bfrag16[l][0][kc][nt][r][lane] = hi;
    g_Bfrag16[l][1][kc][nt][r][lane] = lo;
}

// ---------------- embed: h = relu(x @ W_embed + b_embed) ----------------
__global__ void __launch_bounds__(256) embed_kernel(const float* __restrict__ x,
                                                    const float* __restrict__ We,
                                                    const float* __restrict__ be) {
    __shared__ __align__(16) float sW[11 * HH];
    for (int i = threadIdx.x; i < 11 * HH; i += 256) sW[i] = We[i];
    __syncthreads();
    int warp = threadIdx.x >> 5, lane = threadIdx.x & 31;
    int n = blockIdx.x * 8 + warp;
    if (n >= NN) return;
    float xv = (lane < 11) ? x[(size_t)n * 11 + lane] : 0.f;
    float4 acc = ((const float4*)be)[lane];
    const float4* sWv = (const float4*)sW;
#pragma unroll
    for (int k = 0; k < 11; k++) {
        float a = __shfl_sync(0xffffffffu, xv, k);
        fma4(acc, a, sWv[k * 32 + lane]);
    }
    acc.x = fmaxf(acc.x, 0.f); acc.y = fmaxf(acc.y, 0.f);
    acc.z = fmaxf(acc.z, 0.f); acc.w = fmaxf(acc.w, 0.f);
    g_h[(size_t)n * 32 + lane] = acc;
}

// ---------------- mma.sync fp16 GEMM: g_m(half) = g_h @ W -------------------
#define SA_STRIDE 20   // floats per row (16 + 4 pad)
__global__ void __launch_bounds__(256) gemm_mma_kernel(int layer) {
    __shared__ __align__(16) uint32_t sB[2][16][2][32];   // [p][nt][r][lane] 8KB
    __shared__ __align__(16) float sA[128 * SA_STRIDE];   // 10KB

    int tid = threadIdx.x;
    int warp = tid >> 5, lane = tid & 31;
    int wm = warp >> 1;
    int wn = warp & 1;
    int g = lane >> 2, t = lane & 3;
    size_t rowbase = (size_t)blockIdx.x * 128;

    const float4* hbase = (const float4*)&g_h[rowbase * 32];
    const uint32_t* bsrc = &g_Bfrag16[layer][0][0][0][0][0];

    float d[2][8][4];
#pragma unroll
    for (int mt = 0; mt < 2; mt++)
#pragma unroll
        for (int nt = 0; nt < 8; nt++)
#pragma unroll
            for (int j = 0; j < 4; j++) d[mt][nt][j] = 0.f;

    for (int c = 0; c < 8; c++) {
        if (c) __syncthreads();
#pragma unroll
        for (int p = 0; p < 2; p++) {
            const float4* src = (const float4*)(bsrc + (size_t)p * 8192 + c * 1024);
            ((float4*)sB)[p * 256 + tid] = src[tid];
        }
#pragma unroll
        for (int i = tid; i < 512; i += 256) {
            int r = i >> 2, q = i & 3;
            ((float4*)sA)[r * 5 + q] = hbase[r * 32 + c * 4 + q];
        }
        __syncthreads();

        uint32_t ah[2][4], al[2][4];
#pragma unroll
        for (int mt = 0; mt < 2; mt++) {
            int row = wm * 32 + mt * 16 + g;
            float2 x0 = *(float2*)&sA[row * SA_STRIDE + 2 * t];
            float2 x1 = *(float2*)&sA[(row + 8) * SA_STRIDE + 2 * t];
            float2 x2 = *(float2*)&sA[row * SA_STRIDE + 2 * t + 8];
            float2 x3 = *(float2*)&sA[(row + 8) * SA_STRIDE + 2 * t + 8];
            split2(x0, ah[mt][0], al[mt][0]);
            split2(x1, ah[mt][1], al[mt][1]);
            split2(x2, ah[mt][2], al[mt][2]);
            split2(x3, ah[mt][3], al[mt][3]);
        }
#pragma unroll
        for (int nt = 0; nt < 8; nt++) {
            int ntg = wn * 8 + nt;
            uint32_t bh0 = sB[0][ntg][0][lane];
            uint32_t bh1 = sB[0][ntg][1][lane];
            uint32_t bl0 = sB[1][ntg][0][lane];
            uint32_t bl1 = sB[1][ntg][1][lane];
#pragma unroll
            for (int mt = 0; mt < 2; mt++) {
                mma_f16(d[mt][nt], ah[mt][0], ah[mt][1], ah[mt][2], ah[mt][3], bh0, bh1);
                mma_f16(d[mt][nt], ah[mt][0], ah[mt][1], ah[mt][2], ah[mt][3], bl0, bl1);
                mma_f16(d[mt][nt], al[mt][0], al[mt][1], al[mt][2], al[mt][3], bh0, bh1);
            }
        }
    }

#pragma unroll
    for (int mt = 0; mt < 2; mt++) {
        size_t row = rowbase + wm * 32 + mt * 16 + g;
#pragma unroll
        for (int nt = 0; nt < 8; nt++) {
            int colh = wn * 32 + nt * 4 + t;
            g_m[row * 64 + colh]       = __floats2half2_rn(d[mt][nt][0], d[mt][nt][1]);
            g_m[(row + 8) * 64 + colh] = __floats2half2_rn(d[mt][nt][2], d[mt][nt][3]);
        }
    }
}

// ---------------- fused aggregate + bias + LN + relu + residual ----------------
// Half-warp per row: 16 lanes x uint4 = 256B fp16 row; 2 edges per warp-load.
__global__ void __launch_bounds__(256) agg_kernel(const float* __restrict__ b,
                                                  const float* __restrict__ gam,
                                                  const float* __restrict__ bet) {
    int warp = threadIdx.x >> 5, lane = threadIdx.x & 31;
    int half = lane >> 4, sl = lane & 15;
    int n = blockIdx.x * 8 + warp;
    if (n >= NN) return;

    const uint4* Mv = (const uint4*)g_m;   // 16 x uint4 per row (8 halves each)

    float acc[8];
#pragma unroll
    for (int j = 0; j < 8; j++) acc[j] = 0.f;

    if (half == 0) {                        // self loop (half 0 only)
        float dn = g_dis[n];
        fma_h8(acc, dn * dn, Mv[(size_t)n * 16 + sl]);
    }

    int beg = g_rowptr[n], end = g_rowptr[n + 1];
    int e = beg + half;                     // half 0: even edges, half 1: odd
    for (; e + 6 < end; e += 8) {
        uint2 c0 = g_cw[e],     c1 = g_cw[e + 2];
        uint2 c2 = g_cw[e + 4], c3 = g_cw[e + 6];
        uint4 u0 = Mv[(size_t)c0.x * 16 + sl];
        uint4 u1 = Mv[(size_t)c1.x * 16 + sl];
        uint4 u2 = Mv[(size_t)c2.x * 16 + sl];
        uint4 u3 = Mv[(size_t)c3.x * 16 + sl];
        fma_h8(acc, __uint_as_float(c0.y), u0);
        fma_h8(acc, __uint_as_float(c1.y), u1);
        fma_h8(acc, __uint_as_float(c2.y), u2);
        fma_h8(acc, __uint_as_float(c3.y), u3);
    }
    for (; e < end; e += 2) {
        uint2 cw = g_cw[e];
        fma_h8(acc, __uint_as_float(cw.y), Mv[(size_t)cw.x * 16 + sl]);
    }

    // combine the two halves (each column now lives in lanes sl and sl+16)
#pragma unroll
    for (int j = 0; j < 8; j++)
        acc[j] += __shfl_xor_sync(0xffffffffu, acc[j], 16);

    // bias
    float4 b0 = ((const float4*)b)[sl * 2];
    float4 b1 = ((const float4*)b)[sl * 2 + 1];
    acc[0] += b0.x; acc[1] += b0.y; acc[2] += b0.z; acc[3] += b0.w;
    acc[4] += b1.x; acc[5] += b1.y; acc[6] += b1.z; acc[7] += b1.w;

    // LN stats (columns duplicated across halves -> normalize by 256)
    float tot = 0.f;
#pragma unroll
    for (int j = 0; j < 8; j++) tot += acc[j];
    float mu = warp_sum(tot) * (1.f / 256.f);
    float dd[8], sq = 0.f;
#pragma unroll
    for (int j = 0; j < 8; j++) { dd[j] = acc[j] - mu; sq += dd[j] * dd[j]; }
    float var = warp_sum(sq) * (1.f / 256.f);
    float inv = rsqrtf(var + 1e-5f);

    if (half == 0) {
        float4 g0 = ((const float4*)gam)[sl * 2];
        float4 g1 = ((const float4*)gam)[sl * 2 + 1];
        float4 t0 = ((const float4*)bet)[sl * 2];
        float4 t1 = ((const float4*)bet)[sl * 2 + 1];
        float4 h0 = g_h[(size_t)n * 32 + sl * 2];
        float4 h1 = g_h[(size_t)n * 32 + sl * 2 + 1];
        float4 o0, o1;
        o0.x = fmaxf(dd[0] * inv * g0.x + t0.x, 0.f) + h0.x;
        o0.y = fmaxf(dd[1] * inv * g0.y + t0.y, 0.f) + h0.y;
        o0.z = fmaxf(dd[2] * inv * g0.z + t0.z, 0.f) + h0.z;
        o0.w = fmaxf(dd[3] * inv * g0.w + t0.w, 0.f) + h0.w;
        o1.x = fmaxf(dd[4] * inv * g1.x + t1.x, 0.f) + h1.x;
        o1.y = fmaxf(dd[5] * inv * g1.y + t1.y, 0.f) + h1.y;
        o1.z = fmaxf(dd[6] * inv * g1.z + t1.z, 0.f) + h1.z;
        o1.w = fmaxf(dd[7] * inv * g1.w + t1.w, 0.f) + h1.w;
        g_h[(size_t)n * 32 + sl * 2]     = o0;
        g_h[(size_t)n * 32 + sl * 2 + 1] = o1;
    }
}

// ---------------- pooling ----------------
__global__ void __launch_bounds__(256) pool_kernel(const int* __restrict__ batch,
                                                   const float* __restrict__ Wout) {
    int warp = threadIdx.x >> 5, lane = threadIdx.x & 31;
    int n = blockIdx.x * 8 + warp;
    if (n >= NN) return;
    float4 hv = g_h[(size_t)n * 32 + lane];
    float4 wv = ((const float4*)Wout)[lane];
    float p = warp_sum(hv.x * wv.x + hv.y * wv.y + hv.z * wv.z + hv.w * wv.w);
    if (lane == 0) {
        int gidx = batch[n];
        atomicAdd(&g_gsum[gidx], p);
        atomicAdd(&g_gcnt[gidx], 1.f);
    }
}

__global__ void out_kernel(float* __restrict__ out, const float* __restrict__ bout) {
    int gidx = blockIdx.x * blockDim.x + threadIdx.x;
    if (gidx < GG)
        out[gidx] = g_gsum[gidx] / fmaxf(g_gcnt[gidx], 1.f) + bout[0];
}

// ---------------- launch ----------------
extern "C" void kernel_launch(void* const* d_in, const int* in_sizes, int n_in,
                              void* d_out, int out_size) {
    const float* x      = (const float*)d_in[0];
    const int*   eidx   = (const int*)d_in[1];    // int32 (JAX x64 disabled)
    const int*   batch  = (const int*)d_in[2];    // int32
    const float* Wemb   = (const float*)d_in[3];
    const float* bemb   = (const float*)d_in[4];
    const float* Wgnn   = (const float*)d_in[5];
    const float* bgnn   = (const float*)d_in[6];
    const float* gamma  = (const float*)d_in[7];
    const float* beta   = (const float*)d_in[8];
    const float* Wout   = (const float*)d_in[9];
    const float* bout   = (const float*)d_in[10];
    float* out = (float*)d_out;

    const int* src = eidx;
    const int* dst = eidx + EE;

    int nb_scan = (NN + 1023) / 1024;  // 98

    zero_kernel<<<(NN + 255) / 256, 256>>>();
    count_kernel<<<(EE + 255) / 256, 256>>>(dst);
    prep_kernel<<<128, 256>>>(Wgnn);
    dis_kernel<<<(NN + 255) / 256, 256>>>();
    scan1_kernel<<<nb_scan, 1024>>>();
    scan2_kernel<<<1, 128>>>(nb_scan);
    scan3_kernel<<<nb_scan, 1024>>>();
    fill_kernel<<<(EE + 255) / 256, 256>>>(src, dst);

    embed_kernel<<<NN / 8, 256>>>(x, Wemb, bemb);

    for (int l = 0; l < LL; l++) {
        gemm_mma_kernel<<<NT, 256>>>(l);
        agg_kernel<<<NN / 8, 256>>>(bgnn + l * HH, gamma + l * HH, beta + l * HH);
    }

    pool_kernel<<<NN / 8, 256>>>(batch, Wout);
    out_kernel<<<(GG + 255) / 256, 256>>>(out, bout);
}

// round 10
// speedup vs baseline: 1.2414x; 1.2414x over previous
#include <cuda_runtime.h>
#include <cuda_fp16.h>
#include <cstdint>

#define NN 100000
#define EE 1600000
#define GG 4096
#define HH 128
#define LL 4
#define NT 782                  // ceil(100000/128) row-tiles of 128
#define NPAD (NT * 128)         // 100096

// ---------------- device scratch (no allocations allowed) ----------------
__device__ int     g_deg[NN];
__device__ int     g_cursor[NN];
__device__ int     g_rowptr[NN + 1];
__device__ uint2   g_cw[EE];                 // (src idx, weight bits) fused
__device__ float   g_dis[NN];
__device__ float4  g_h[(size_t)NPAD * 32];   // N x 128 fp32 (padded, zero-init)
__device__ __half2 g_m[(size_t)NPAD * 64];   // N x 128 fp16 (padded)
__device__ float   g_gsum[GG];
__device__ float   g_gcnt[GG];
__device__ int     g_blocksums[128];
__device__ int     g_blockoffs[128];
// W in m16n8k16 fragment layout, fp16 hi/lo: [L][p][kc 8][nt 16][r 2][lane 32]
__device__ uint32_t g_Bfrag16[LL][2][8][16][2][32];

// ---------------- helpers ----------------
__device__ __forceinline__ float warp_sum(float v) {
#pragma unroll
    for (int o = 16; o; o >>= 1) v += __shfl_xor_sync(0xffffffffu, v, o);
    return v;
}
__device__ __forceinline__ void fma4(float4& acc, float a, const float4& w) {
    acc.x = fmaf(a, w.x, acc.x);
    acc.y = fmaf(a, w.y, acc.y);
    acc.z = fmaf(a, w.z, acc.z);
    acc.w = fmaf(a, w.w, acc.w);
}
__device__ __forceinline__ void fma_h4(float4& acc, float w, uint2 u) {
    __half2 p0 = *(__half2*)&u.x;
    __half2 p1 = *(__half2*)&u.y;
    float2 f0 = __half22float2(p0);
    float2 f1 = __half22float2(p1);
    acc.x = fmaf(w, f0.x, acc.x);
    acc.y = fmaf(w, f0.y, acc.y);
    acc.z = fmaf(w, f1.x, acc.z);
    acc.w = fmaf(w, f1.y, acc.w);
}
// fp16 hi/lo split of a float2, packed as half2 words (W prep only)
__device__ __forceinline__ void split2(float2 v, uint32_t& hi, uint32_t& lo) {
    __half hx = __float2half_rn(v.x), hy = __float2half_rn(v.y);
    __half lx = __float2half_rn(v.x - __half2float(hx));
    __half ly = __float2half_rn(v.y - __half2float(hy));
    __half2 h2 = __halves2half2(hx, hy);
    __half2 l2 = __halves2half2(lx, ly);
    hi = *(uint32_t*)&h2;
    lo = *(uint32_t*)&l2;
}
__device__ __forceinline__ uint32_t pack_h2(float2 v) {
    __half2 h = __floats2half2_rn(v.x, v.y);
    return *(uint32_t*)&h;
}
__device__ __forceinline__ void mma_f16(float* d, uint32_t a0, uint32_t a1,
                                        uint32_t a2, uint32_t a3,
                                        uint32_t b0, uint32_t b1) {
    asm("mma.sync.aligned.m16n8k16.row.col.f32.f16.f16.f32 "
        "{%0,%1,%2,%3},{%4,%5,%6,%7},{%8,%9},{%0,%1,%2,%3};"
        : "+f"(d[0]), "+f"(d[1]), "+f"(d[2]), "+f"(d[3])
        : "r"(a0), "r"(a1), "r"(a2), "r"(a3), "r"(b0), "r"(b1));
}

// ---------------- setup kernels ----------------
__global__ void zero_kernel() {
    int i = blockIdx.x * blockDim.x + threadIdx.x;
    if (i < NN) { g_deg[i] = 0; g_cursor[i] = 0; }
    if (i < GG) { g_gsum[i] = 0.f; g_gcnt[i] = 0.f; }
}

__global__ void count_kernel(const int* __restrict__ dst) {
    int e = blockIdx.x * blockDim.x + threadIdx.x;
    if (e < EE) atomicAdd(&g_deg[dst[e]], 1);
}

__global__ void dis_kernel() {
    int i = blockIdx.x * blockDim.x + threadIdx.x;
    if (i < NN) g_dis[i] = rsqrtf((float)(g_deg[i] + 1));
}

__global__ void scan1_kernel() {
    __shared__ int sh[1024];
    int tid = threadIdx.x;
    int idx = blockIdx.x * 1024 + tid;
    int v = (idx < NN) ? g_deg[idx] : 0;
    sh[tid] = v;
    __syncthreads();
#pragma unroll
    for (int off = 1; off < 1024; off <<= 1) {
        int t = (tid >= off) ? sh[tid - off] : 0;
        __syncthreads();
        sh[tid] += t;
        __syncthreads();
    }
    if (idx < NN) g_rowptr[idx] = sh[tid] - v;
    if (tid == 1023) g_blocksums[blockIdx.x] = sh[1023];
}

__global__ void scan2_kernel(int nblocks) {
    __shared__ int sh[128];
    int tid = threadIdx.x;
    int v = (tid < nblocks) ? g_blocksums[tid] : 0;
    sh[tid] = v;
    __syncthreads();
#pragma unroll
    for (int off = 1; off < 128; off <<= 1) {
        int t = (tid >= off) ? sh[tid - off] : 0;
        __syncthreads();
        sh[tid] += t;
        __syncthreads();
    }
    if (tid < nblocks) g_blockoffs[tid] = sh[tid] - v;
    if (tid == 0) g_rowptr[NN] = EE;
}

__global__ void scan3_kernel() {
    int idx = blockIdx.x * 1024 + threadIdx.x;
    if (idx < NN) g_rowptr[idx] += g_blockoffs[blockIdx.x];
}

__global__ void fill_kernel(const int* __restrict__ src, const int* __restrict__ dst) {
    int e = blockIdx.x * blockDim.x + threadIdx.x;
    if (e >= EE) return;
    int s = src[e];
    int d = dst[e];
    int pos = g_rowptr[d] + atomicAdd(&g_cursor[d], 1);
    g_cw[pos] = make_uint2((unsigned)s, __float_as_uint(g_dis[s] * g_dis[d]));
}

// ---------------- W prep: fp16 hi/lo split into m16n8k16 fragment layout -------
__global__ void prep_kernel(const float* __restrict__ Wgnn) {
    int idx = blockIdx.x * 256 + threadIdx.x;
    if (idx >= LL * 8 * 16 * 2 * 32) return;
    int lane = idx & 31;
    int r    = (idx >> 5) & 1;
    int nt   = (idx >> 6) & 15;
    int kc   = (idx >> 10) & 7;
    int l    = idx >> 13;
    int t = lane & 3, g = lane >> 2;
    int k0 = kc * 16 + r * 8 + 2 * t;
    int n  = nt * 8 + g;
    float w0 = Wgnn[(size_t)l * 16384 + k0 * 128 + n];
    float w1 = Wgnn[(size_t)l * 16384 + (k0 + 1) * 128 + n];
    uint32_t hi, lo;
    split2(make_float2(w0, w1), hi, lo);
    g_Bfrag16[l][0][kc][nt][r][lane] = hi;
    g_Bfrag16[l][1][kc][nt][r][lane] = lo;
}

// ---------------- embed: h = relu(x @ W_embed + b_embed) ----------------
__global__ void __launch_bounds__(256) embed_kernel(const float* __restrict__ x,
                                                    const float* __restrict__ We,
                                                    const float* __restrict__ be) {
    __shared__ __align__(16) float sW[11 * HH];
    for (int i = threadIdx.x; i < 11 * HH; i += 256) sW[i] = We[i];
    __syncthreads();
    int warp = threadIdx.x >> 5, lane = threadIdx.x & 31;
    int n = blockIdx.x * 8 + warp;
    if (n >= NN) return;
    float xv = (lane < 11) ? x[(size_t)n * 11 + lane] : 0.f;
    float4 acc = ((const float4*)be)[lane];
    const float4* sWv = (const float4*)sW;
#pragma unroll
    for (int k = 0; k < 11; k++) {
        float a = __shfl_sync(0xffffffffu, xv, k);
        fma4(acc, a, sWv[k * 32 + lane]);
    }
    acc.x = fmaxf(acc.x, 0.f); acc.y = fmaxf(acc.y, 0.f);
    acc.z = fmaxf(acc.z, 0.f); acc.w = fmaxf(acc.w, 0.f);
    g_h[(size_t)n * 32 + lane] = acc;
}

// ---------------- mma.sync fp16 GEMM: g_m(half) = g_h @ W -------------------
// 2-pass: A quantized to fp16 (ah), W split hi/lo: ah*bh + ah*bl.
#define SA_STRIDE 20   // floats per row (16 + 4 pad)
__global__ void __launch_bounds__(256) gemm_mma_kernel(int layer) {
    __shared__ __align__(16) uint32_t sB[2][16][2][32];   // [p][nt][r][lane] 8KB
    __shared__ __align__(16) float sA[128 * SA_STRIDE];   // 10KB

    int tid = threadIdx.x;
    int warp = tid >> 5, lane = tid & 31;
    int wm = warp >> 1;
    int wn = warp & 1;
    int g = lane >> 2, t = lane & 3;
    size_t rowbase = (size_t)blockIdx.x * 128;

    const float4* hbase = (const float4*)&g_h[rowbase * 32];
    const uint32_t* bsrc = &g_Bfrag16[layer][0][0][0][0][0];

    float d[2][8][4];
#pragma unroll
    for (int mt = 0; mt < 2; mt++)
#pragma unroll
        for (int nt = 0; nt < 8; nt++)
#pragma unroll
            for (int j = 0; j < 4; j++) d[mt][nt][j] = 0.f;

    for (int c = 0; c < 8; c++) {
        if (c) __syncthreads();
#pragma unroll
        for (int p = 0; p < 2; p++) {
            const float4* src = (const float4*)(bsrc + (size_t)p * 8192 + c * 1024);
            ((float4*)sB)[p * 256 + tid] = src[tid];
        }
#pragma unroll
        for (int i = tid; i < 512; i += 256) {
            int r = i >> 2, q = i & 3;
            ((float4*)sA)[r * 5 + q] = hbase[r * 32 + c * 4 + q];
        }
        __syncthreads();

        uint32_t ah[2][4];
#pragma unroll
        for (int mt = 0; mt < 2; mt++) {
            int row = wm * 32 + mt * 16 + g;
            ah[mt][0] = pack_h2(*(float2*)&sA[row * SA_STRIDE + 2 * t]);
            ah[mt][1] = pack_h2(*(float2*)&sA[(row + 8) * SA_STRIDE + 2 * t]);
            ah[mt][2] = pack_h2(*(float2*)&sA[row * SA_STRIDE + 2 * t + 8]);
            ah[mt][3] = pack_h2(*(float2*)&sA[(row + 8) * SA_STRIDE + 2 * t + 8]);
        }
#pragma unroll
        for (int nt = 0; nt < 8; nt++) {
            int ntg = wn * 8 + nt;
            uint32_t bh0 = sB[0][ntg][0][lane];
            uint32_t bh1 = sB[0][ntg][1][lane];
            uint32_t bl0 = sB[1][ntg][0][lane];
            uint32_t bl1 = sB[1][ntg][1][lane];
#pragma unroll
            for (int mt = 0; mt < 2; mt++) {
                mma_f16(d[mt][nt], ah[mt][0], ah[mt][1], ah[mt][2], ah[mt][3], bh0, bh1);
                mma_f16(d[mt][nt], ah[mt][0], ah[mt][1], ah[mt][2], ah[mt][3], bl0, bl1);
            }
        }
    }

#pragma unroll
    for (int mt = 0; mt < 2; mt++) {
        size_t row = rowbase + wm * 32 + mt * 16 + g;
#pragma unroll
        for (int nt = 0; nt < 8; nt++) {
            int colh = wn * 32 + nt * 4 + t;
            g_m[row * 64 + colh]       = __floats2half2_rn(d[mt][nt][0], d[mt][nt][1]);
            g_m[(row + 8) * 64 + colh] = __floats2half2_rn(d[mt][nt][2], d[mt][nt][3]);
        }
    }
}

// ---------------- fused aggregate + bias + LN + relu + residual ----------------
__global__ void __launch_bounds__(256) agg_kernel(const float* __restrict__ b,
                                                  const float* __restrict__ gam,
                                                  const float* __restrict__ bet) {
    int warp = threadIdx.x >> 5, lane = threadIdx.x & 31;
    int n = blockIdx.x * 8 + warp;
    if (n >= NN) return;

    const uint2* Mv = (const uint2*)g_m;   // 32 x uint2 per row (4 halves each)

    float dn = g_dis[n];
    float4 acc = make_float4(0.f, 0.f, 0.f, 0.f);
    fma_h4(acc, dn * dn, Mv[(size_t)n * 32 + lane]);   // self loop

    int beg = g_rowptr[n], end = g_rowptr[n + 1];
    int e = beg;
    for (; e + 4 <= end; e += 4) {
        uint2 c0 = g_cw[e],     c1 = g_cw[e + 1];
        uint2 c2 = g_cw[e + 2], c3 = g_cw[e + 3];
        uint2 u0 = Mv[(size_t)c0.x * 32 + lane];
        uint2 u1 = Mv[(size_t)c1.x * 32 + lane];
        uint2 u2 = Mv[(size_t)c2.x * 32 + lane];
        uint2 u3 = Mv[(size_t)c3.x * 32 + lane];
        fma_h4(acc, __uint_as_float(c0.y), u0);
        fma_h4(acc, __uint_as_float(c1.y), u1);
        fma_h4(acc, __uint_as_float(c2.y), u2);
        fma_h4(acc, __uint_as_float(c3.y), u3);
    }
    for (; e < end; e++) {
        uint2 cw = g_cw[e];
        fma_h4(acc, __uint_as_float(cw.y), Mv[(size_t)cw.x * 32 + lane]);
    }
    float4 bb = ((const float4*)b)[lane];
    acc.x += bb.x; acc.y += bb.y; acc.z += bb.z; acc.w += bb.w;

    float mu = warp_sum(acc.x + acc.y + acc.z + acc.w) * (1.f / 128.f);
    float4 dd = make_float4(acc.x - mu, acc.y - mu, acc.z - mu, acc.w - mu);
    float var = warp_sum(dd.x * dd.x + dd.y * dd.y + dd.z * dd.z + dd.w * dd.w) * (1.f / 128.f);
    float inv = rsqrtf(var + 1e-5f);

    float4 gg = ((const float4*)gam)[lane];
    float4 bt = ((const float4*)bet)[lane];
    float4 hv = g_h[(size_t)n * 32 + lane];
    float4 o;
    o.x = fmaxf(dd.x * inv * gg.x + bt.x, 0.f) + hv.x;
    o.y = fmaxf(dd.y * inv * gg.y + bt.y, 0.f) + hv.y;
    o.z = fmaxf(dd.z * inv * gg.z + bt.z, 0.f) + hv.z;
    o.w = fmaxf(dd.w * inv * gg.w + bt.w, 0.f) + hv.w;
    g_h[(size_t)n * 32 + lane] = o;
}

// ---------------- pooling ----------------
__global__ void __launch_bounds__(256) pool_kernel(const int* __restrict__ batch,
                                                   const float* __restrict__ Wout) {
    int warp = threadIdx.x >> 5, lane = threadIdx.x & 31;
    int n = blockIdx.x * 8 + warp;
    if (n >= NN) return;
    float4 hv = g_h[(size_t)n * 32 + lane];
    float4 wv = ((const float4*)Wout)[lane];
    float p = warp_sum(hv.x * wv.x + hv.y * wv.y + hv.z * wv.z + hv.w * wv.w);
    if (lane == 0) {
        int gidx = batch[n];
        atomicAdd(&g_gsum[gidx], p);
        atomicAdd(&g_gcnt[gidx], 1.f);
    }
}

__global__ void out_kernel(float* __restrict__ out, const float* __restrict__ bout) {
    int gidx = blockIdx.x * blockDim.x + threadIdx.x;
    if (gidx < GG)
        out[gidx] = g_gsum[gidx] / fmaxf(g_gcnt[gidx], 1.f) + bout[0];
}

// ---------------- launch ----------------
extern "C" void kernel_launch(void* const* d_in, const int* in_sizes, int n_in,
                              void* d_out, int out_size) {
    const float* x      = (const float*)d_in[0];
    const int*   eidx   = (const int*)d_in[1];    // int32 (JAX x64 disabled)
    const int*   batch  = (const int*)d_in[2];    // int32
    const float* Wemb   = (const float*)d_in[3];
    const float* bemb   = (const float*)d_in[4];
    const float* Wgnn   = (const float*)d_in[5];
    const float* bgnn   = (const float*)d_in[6];
    const float* gamma  = (const float*)d_in[7];
    const float* beta   = (const float*)d_in[8];
    const float* Wout   = (const float*)d_in[9];
    const float* bout   = (const float*)d_in[10];
    float* out = (float*)d_out;

    const int* src = eidx;
    const int* dst = eidx + EE;

    int nb_scan = (NN + 1023) / 1024;  // 98

    zero_kernel<<<(NN + 255) / 256, 256>>>();
    count_kernel<<<(EE + 255) / 256, 256>>>(dst);
    prep_kernel<<<128, 256>>>(Wgnn);
    dis_kernel<<<(NN + 255) / 256, 256>>>();
    scan1_kernel<<<nb_scan, 1024>>>();
    scan2_kernel<<<1, 128>>>(nb_scan);
    scan3_kernel<<<nb_scan, 1024>>>();
    fill_kernel<<<(EE + 255) / 256, 256>>>(src, dst);

    embed_kernel<<<NN / 8, 256>>>(x, Wemb, bemb);

    for (int l = 0; l < LL; l++) {
        gemm_mma_kernel<<<NT, 256>>>(l);
        agg_kernel<<<NN / 8, 256>>>(bgnn + l * HH, gamma + l * HH, beta + l * HH);
    }

    pool_kernel<<<NN / 8, 256>>>(batch, Wout);
    out_kernel<<<(GG + 255) / 256, 256>>>(out, bout);
}

// round 12
// speedup vs baseline: 1.3763x; 1.1087x over previous
#include <cuda_runtime.h>
#include <cuda_fp16.h>
#include <cstdint>

#define NN 100000
#define EE 1600000
#define GG 4096
#define HH 128
#define LL 4
#define NT 782                  // ceil(100000/128) row-tiles of 128
#define NPAD (NT * 128)         // 100096

// ---------------- device scratch (no allocations allowed) ----------------
__device__ int     g_deg[NN];
__device__ int     g_cursor[NN];
__device__ int     g_rowptr[NN + 1];
__device__ uint2   g_cw[EE];                 // (src idx, weight bits) fused
__device__ float   g_dis[NN];
__device__ __align__(16) __half2 g_h[(size_t)NPAD * 64];   // N x 128 fp16 residual (zero-init)
__device__ __align__(16) __half2 g_m[(size_t)NPAD * 64];   // N x 128 fp16 (padded)
__device__ float   g_gsum[GG];
__device__ float   g_gcnt[GG];
__device__ int     g_blocksums[128];
__device__ int     g_blockoffs[128];
// W in m16n8k16 fragment layout, fp16 hi/lo: [L][p][kc 8][nt 16][r 2][lane 32]
__device__ uint32_t g_Bfrag16[LL][2][8][16][2][32];

// ---------------- helpers ----------------
__device__ __forceinline__ float warp_sum(float v) {
#pragma unroll
    for (int o = 16; o; o >>= 1) v += __shfl_xor_sync(0xffffffffu, v, o);
    return v;
}
__device__ __forceinline__ void fma4(float4& acc, float a, const float4& w) {
    acc.x = fmaf(a, w.x, acc.x);
    acc.y = fmaf(a, w.y, acc.y);
    acc.z = fmaf(a, w.z, acc.z);
    acc.w = fmaf(a, w.w, acc.w);
}
__device__ __forceinline__ void fma_h4(float4& acc, float w, uint2 u) {
    float2 f0 = __half22float2(*(__half2*)&u.x);
    float2 f1 = __half22float2(*(__half2*)&u.y);
    acc.x = fmaf(w, f0.x, acc.x);
    acc.y = fmaf(w, f0.y, acc.y);
    acc.z = fmaf(w, f1.x, acc.z);
    acc.w = fmaf(w, f1.y, acc.w);
}
__device__ __forceinline__ float4 h4_to_f4(uint2 u) {
    float2 f0 = __half22float2(*(__half2*)&u.x);
    float2 f1 = __half22float2(*(__half2*)&u.y);
    return make_float4(f0.x, f0.y, f1.x, f1.y);
}
__device__ __forceinline__ uint32_t pack_h2(float2 v) {
    __half2 h = __floats2half2_rn(v.x, v.y);
    return *(uint32_t*)&h;
}
__device__ __forceinline__ uint2 pack_h4(float4 v) {
    return make_uint2(pack_h2(make_float2(v.x, v.y)), pack_h2(make_float2(v.z, v.w)));
}
// fp16 hi/lo split of a float2 (W prep only)
__device__ __forceinline__ void split2(float2 v, uint32_t& hi, uint32_t& lo) {
    __half hx = __float2half_rn(v.x), hy = __float2half_rn(v.y);
    __half lx = __float2half_rn(v.x - __half2float(hx));
    __half ly = __float2half_rn(v.y - __half2float(hy));
    __half2 h2 = __halves2half2(hx, hy);
    __half2 l2 = __halves2half2(lx, ly);
    hi = *(uint32_t*)&h2;
    lo = *(uint32_t*)&l2;
}
__device__ __forceinline__ void mma_f16(float* d, uint32_t a0, uint32_t a1,
                                        uint32_t a2, uint32_t a3,
                                        uint32_t b0, uint32_t b1) {
    asm("mma.sync.aligned.m16n8k16.row.col.f32.f16.f16.f32 "
        "{%0,%1,%2,%3},{%4,%5,%6,%7},{%8,%9},{%0,%1,%2,%3};"
        : "+f"(d[0]), "+f"(d[1]), "+f"(d[2]), "+f"(d[3])
        : "r"(a0), "r"(a1), "r"(a2), "r"(a3), "r"(b0), "r"(b1));
}

// ---------------- setup kernels ----------------
__global__ void zero_kernel() {
    int i = blockIdx.x * blockDim.x + threadIdx.x;
    if (i < NN) { g_deg[i] = 0; g_cursor[i] = 0; }
    if (i < GG) { g_gsum[i] = 0.f; g_gcnt[i] = 0.f; }
}

__global__ void count_kernel(const int* __restrict__ dst) {
    int e = blockIdx.x * blockDim.x + threadIdx.x;
    if (e < EE) atomicAdd(&g_deg[dst[e]], 1);
}

__global__ void dis_kernel() {
    int i = blockIdx.x * blockDim.x + threadIdx.x;
    if (i < NN) g_dis[i] = rsqrtf((float)(g_deg[i] + 1));
}

__global__ void scan1_kernel() {
    __shared__ int sh[1024];
    int tid = threadIdx.x;
    int idx = blockIdx.x * 1024 + tid;
    int v = (idx < NN) ? g_deg[idx] : 0;
    sh[tid] = v;
    __syncthreads();
#pragma unroll
    for (int off = 1; off < 1024; off <<= 1) {
        int t = (tid >= off) ? sh[tid - off] : 0;
        __syncthreads();
        sh[tid] += t;
        __syncthreads();
    }
    if (idx < NN) g_rowptr[idx] = sh[tid] - v;
    if (tid == 1023) g_blocksums[blockIdx.x] = sh[1023];
}

__global__ void scan2_kernel(int nblocks) {
    __shared__ int sh[128];
    int tid = threadIdx.x;
    int v = (tid < nblocks) ? g_blocksums[tid] : 0;
    sh[tid] = v;
    __syncthreads();
#pragma unroll
    for (int off = 1; off < 128; off <<= 1) {
        int t = (tid >= off) ? sh[tid - off] : 0;
        __syncthreads();
        sh[tid] += t;
        __syncthreads();
    }
    if (tid < nblocks) g_blockoffs[tid] = sh[tid] - v;
    if (tid == 0) g_rowptr[NN] = EE;
}

__global__ void scan3_kernel() {
    int idx = blockIdx.x * 1024 + threadIdx.x;
    if (idx < NN) g_rowptr[idx] += g_blockoffs[blockIdx.x];
}

__global__ void fill_kernel(const int* __restrict__ src, const int* __restrict__ dst) {
    int e = blockIdx.x * blockDim.x + threadIdx.x;
    if (e >= EE) return;
    int s = src[e];
    int d = dst[e];
    int pos = g_rowptr[d] + atomicAdd(&g_cursor[d], 1);
    g_cw[pos] = make_uint2((unsigned)s, __float_as_uint(g_dis[s] * g_dis[d]));
}

// ---------------- W prep: fp16 hi/lo split into m16n8k16 fragment layout -------
__global__ void prep_kernel(const float* __restrict__ Wgnn) {
    int idx = blockIdx.x * 256 + threadIdx.x;
    if (idx >= LL * 8 * 16 * 2 * 32) return;
    int lane = idx & 31;
    int r    = (idx >> 5) & 1;
    int nt   = (idx >> 6) & 15;
    int kc   = (idx >> 10) & 7;
    int l    = idx >> 13;
    int t = lane & 3, g = lane >> 2;
    int k0 = kc * 16 + r * 8 + 2 * t;
    int n  = nt * 8 + g;
    float w0 = Wgnn[(size_t)l * 16384 + k0 * 128 + n];
    float w1 = Wgnn[(size_t)l * 16384 + (k0 + 1) * 128 + n];
    uint32_t hi, lo;
    split2(make_float2(w0, w1), hi, lo);
    g_Bfrag16[l][0][kc][nt][r][lane] = hi;
    g_Bfrag16[l][1][kc][nt][r][lane] = lo;
}

// ---------------- embed: h = relu(x @ W_embed + b_embed), fp16 out ------------
__global__ void __launch_bounds__(256) embed_kernel(const float* __restrict__ x,
                                                    const float* __restrict__ We,
                                                    const float* __restrict__ be) {
    __shared__ __align__(16) float sW[11 * HH];
    for (int i = threadIdx.x; i < 11 * HH; i += 256) sW[i] = We[i];
    __syncthreads();
    int warp = threadIdx.x >> 5, lane = threadIdx.x & 31;
    int n = blockIdx.x * 8 + warp;
    if (n >= NN) return;
    float xv = (lane < 11) ? x[(size_t)n * 11 + lane] : 0.f;
    float4 acc = ((const float4*)be)[lane];
    const float4* sWv = (const float4*)sW;
#pragma unroll
    for (int k = 0; k < 11; k++) {
        float a = __shfl_sync(0xffffffffu, xv, k);
        fma4(acc, a, sWv[k * 32 + lane]);
    }
    acc.x = fmaxf(acc.x, 0.f); acc.y = fmaxf(acc.y, 0.f);
    acc.z = fmaxf(acc.z, 0.f); acc.w = fmaxf(acc.w, 0.f);
    ((uint2*)g_h)[(size_t)n * 32 + lane] = pack_h4(acc);
}

// ---------------- mma.sync fp16 GEMM: g_m(half) = g_h(half) @ W ---------------
// 2-pass W hi/lo; A is fp16 in global, loaded straight into fragments.
#define SA_STRIDE 12   // uints per row (8 + 4 pad)
__global__ void __launch_bounds__(256) gemm_mma_kernel(int layer) {
    __shared__ __align__(16) uint32_t sB[2][16][2][32];   // [p][nt][r][lane] 8KB
    __shared__ __align__(16) uint32_t sA[128 * SA_STRIDE]; // 6KB

    int tid = threadIdx.x;
    int warp = tid >> 5, lane = tid & 31;
    int wm = warp >> 1;
    int wn = warp & 1;
    int g = lane >> 2, t = lane & 3;
    size_t rowbase = (size_t)blockIdx.x * 128;

    const uint4* hbase = (const uint4*)&g_h[rowbase * 64];   // 16 x uint4 per row
    const uint32_t* bsrc = &g_Bfrag16[layer][0][0][0][0][0];

    float d[2][8][4];
#pragma unroll
    for (int mt = 0; mt < 2; mt++)
#pragma unroll
        for (int nt = 0; nt < 8; nt++)
#pragma unroll
            for (int j = 0; j < 4; j++) d[mt][nt][j] = 0.f;

    int r_ = tid >> 1, seg = tid & 1;
    for (int c = 0; c < 8; c++) {
        if (c) __syncthreads();
#pragma unroll
        for (int p = 0; p < 2; p++) {
            const float4* src = (const float4*)(bsrc + (size_t)p * 8192 + c * 1024);
            ((float4*)sB)[p * 256 + tid] = src[tid];
        }
        // A chunk: 128 rows x 16 halves (2 uint4 per row, ROW STRIDE 16 uint4)
        ((uint4*)(sA + r_ * SA_STRIDE))[seg] = hbase[r_ * 16 + c * 2 + seg];
        __syncthreads();

        uint32_t ah[2][4];
#pragma unroll
        for (int mt = 0; mt < 2; mt++) {
            int row = wm * 32 + mt * 16 + g;
            ah[mt][0] = sA[row * SA_STRIDE + t];
            ah[mt][1] = sA[(row + 8) * SA_STRIDE + t];
            ah[mt][2] = sA[row * SA_STRIDE + 4 + t];
            ah[mt][3] = sA[(row + 8) * SA_STRIDE + 4 + t];
        }
#pragma unroll
        for (int nt = 0; nt < 8; nt++) {
            int ntg = wn * 8 + nt;
            uint32_t bh0 = sB[0][ntg][0][lane];
            uint32_t bh1 = sB[0][ntg][1][lane];
            uint32_t bl0 = sB[1][ntg][0][lane];
            uint32_t bl1 = sB[1][ntg][1][lane];
#pragma unroll
            for (int mt = 0; mt < 2; mt++) {
                mma_f16(d[mt][nt], ah[mt][0], ah[mt][1], ah[mt][2], ah[mt][3], bh0, bh1);
                mma_f16(d[mt][nt], ah[mt][0], ah[mt][1], ah[mt][2], ah[mt][3], bl0, bl1);
            }
        }
    }

#pragma unroll
    for (int mt = 0; mt < 2; mt++) {
        size_t row = rowbase + wm * 32 + mt * 16 + g;
#pragma unroll
        for (int nt = 0; nt < 8; nt++) {
            int colh = wn * 32 + nt * 4 + t;
            g_m[row * 64 + colh]       = __floats2half2_rn(d[mt][nt][0], d[mt][nt][1]);
            g_m[(row + 8) * 64 + colh] = __floats2half2_rn(d[mt][nt][2], d[mt][nt][3]);
        }
    }
}

// ---------------- fused aggregate + bias + LN + relu + residual ----------------
__global__ void __launch_bounds__(256) agg_kernel(const float* __restrict__ b,
                                                  const float* __restrict__ gam,
                                                  const float* __restrict__ bet) {
    int warp = threadIdx.x >> 5, lane = threadIdx.x & 31;
    int n = blockIdx.x * 8 + warp;
    if (n >= NN) return;

    const uint2* Mv = (const uint2*)g_m;   // 32 x uint2 per row (4 halves each)
    uint2* Hv = (uint2*)g_h;

    float dn = g_dis[n];
    float4 acc = make_float4(0.f, 0.f, 0.f, 0.f);
    fma_h4(acc, dn * dn, Mv[(size_t)n * 32 + lane]);   // self loop

    int beg = g_rowptr[n], end = g_rowptr[n + 1];
    int e = beg;
    for (; e + 4 <= end; e += 4) {
        uint2 c0 = g_cw[e],     c1 = g_cw[e + 1];
        uint2 c2 = g_cw[e + 2], c3 = g_cw[e + 3];
        uint2 u0 = Mv[(size_t)c0.x * 32 + lane];
        uint2 u1 = Mv[(size_t)c1.x * 32 + lane];
        uint2 u2 = Mv[(size_t)c2.x * 32 + lane];
        uint2 u3 = Mv[(size_t)c3.x * 32 + lane];
        fma_h4(acc, __uint_as_float(c0.y), u0);
        fma_h4(acc, __uint_as_float(c1.y), u1);
        fma_h4(acc, __uint_as_float(c2.y), u2);
        fma_h4(acc, __uint_as_float(c3.y), u3);
    }
    for (; e < end; e++) {
        uint2 cw = g_cw[e];
        fma_h4(acc, __uint_as_float(cw.y), Mv[(size_t)cw.x * 32 + lane]);
    }
    float4 bb = ((const float4*)b)[lane];
    acc.x += bb.x; acc.y += bb.y; acc.z += bb.z; acc.w += bb.w;

    float mu = warp_sum(acc.x + acc.y + acc.z + acc.w) * (1.f / 128.f);
    float4 dd = make_float4(acc.x - mu, acc.y - mu, acc.z - mu, acc.w - mu);
    float var = warp_sum(dd.x * dd.x + dd.y * dd.y + dd.z * dd.z + dd.w * dd.w) * (1.f / 128.f);
    float inv = rsqrtf(var + 1e-5f);

    float4 gg = ((const float4*)gam)[lane];
    float4 bt = ((const float4*)bet)[lane];
    float4 hv = h4_to_f4(Hv[(size_t)n * 32 + lane]);
    float4 o;
    o.x = fmaxf(dd.x * inv * gg.x + bt.x, 0.f) + hv.x;
    o.y = fmaxf(dd.y * inv * gg.y + bt.y, 0.f) + hv.y;
    o.z = fmaxf(dd.z * inv * gg.z + bt.z, 0.f) + hv.z;
    o.w = fmaxf(dd.w * inv * gg.w + bt.w, 0.f) + hv.w;
    Hv[(size_t)n * 32 + lane] = pack_h4(o);
}

// ---------------- pooling ----------------
__global__ void __launch_bounds__(256) pool_kernel(const int* __restrict__ batch,
                                                   const float* __restrict__ Wout) {
    int warp = threadIdx.x >> 5, lane = threadIdx.x & 31;
    int n = blockIdx.x * 8 + warp;
    if (n >= NN) return;
    float4 hv = h4_to_f4(((const uint2*)g_h)[(size_t)n * 32 + lane]);
    float4 wv = ((const float4*)Wout)[lane];
    float p = warp_sum(hv.x * wv.x + hv.y * wv.y + hv.z * wv.z + hv.w * wv.w);
    if (lane == 0) {
        int gidx = batch[n];
        atomicAdd(&g_gsum[gidx], p);
        atomicAdd(&g_gcnt[gidx], 1.f);
    }
}

__global__ void out_kernel(float* __restrict__ out, const float* __restrict__ bout) {
    int gidx = blockIdx.x * blockDim.x + threadIdx.x;
    if (gidx < GG)
        out[gidx] = g_gsum[gidx] / fmaxf(g_gcnt[gidx], 1.f) + bout[0];
}

// ---------------- launch ----------------
extern "C" void kernel_launch(void* const* d_in, const int* in_sizes, int n_in,
                              void* d_out, int out_size) {
    const float* x      = (const float*)d_in[0];
    const int*   eidx   = (const int*)d_in[1];    // int32 (JAX x64 disabled)
    const int*   batch  = (const int*)d_in[2];    // int32
    const float* Wemb   = (const float*)d_in[3];
    const float* bemb   = (const float*)d_in[4];
    const float* Wgnn   = (const float*)d_in[5];
    const float* bgnn   = (const float*)d_in[6];
    const float* gamma  = (const float*)d_in[7];
    const float* beta   = (const float*)d_in[8];
    const float* Wout   = (const float*)d_in[9];
    const float* bout   = (const float*)d_in[10];
    float* out = (float*)d_out;

    const int* src = eidx;
    const int* dst = eidx + EE;

    int nb_scan = (NN + 1023) / 1024;  // 98

    zero_kernel<<<(NN + 255) / 256, 256>>>();
    count_kernel<<<(EE + 255) / 256, 256>>>(dst);
    prep_kernel<<<128, 256>>>(Wgnn);
    dis_kernel<<<(NN + 255) / 256, 256>>>();
    scan1_kernel<<<nb_scan, 1024>>>();
    scan2_kernel<<<1, 128>>>(nb_scan);
    scan3_kernel<<<nb_scan, 1024>>>();
    fill_kernel<<<(EE + 255) / 256, 256>>>(src, dst);

    embed_kernel<<<NN / 8, 256>>>(x, Wemb, bemb);

    for (int l = 0; l < LL; l++) {
        gemm_mma_kernel<<<NT, 256>>>(l);
        agg_kernel<<<NN / 8, 256>>>(bgnn + l * HH, gamma + l * HH, beta + l * HH);
    }

    pool_kernel<<<NN / 8, 256>>>(batch, Wout);
    out_kernel<<<(GG + 255) / 256, 256>>>(out, bout);
}

// round 13
// speedup vs baseline: 1.4476x; 1.0518x over previous
#include <cuda_runtime.h>
#include <cuda_fp16.h>
#include <cstdint>

#define NN 100000
#define EE 1600000
#define GG 4096
#define HH 128
#define LL 4
#define NT 782                  // ceil(100000/128) row-tiles of 128
#define NPAD (NT * 128)         // 100096

#define EMB_BLOCKS 12500        // NN/8
#define ZERO_BLOCKS 391         // ceil(NN/256)
#define PREP_BLOCKS 128

// ---------------- device scratch (no allocations allowed) ----------------
__device__ int     g_deg[NN];
__device__ int     g_cursor[NN];
__device__ int     g_rowptr[NN + 1];
__device__ uint2   g_cw[EE];                 // (src idx, weight bits) fused
__device__ float   g_dis[NN];
__device__ __align__(16) __half2 g_h[(size_t)NPAD * 64];   // N x 128 fp16 residual (zero-init)
__device__ __align__(16) __half2 g_m[(size_t)NPAD * 64];   // N x 128 fp16 (padded)
__device__ float   g_gsum[GG];
__device__ float   g_gcnt[GG];
__device__ int     g_blocksums[128];
__device__ int     g_blockoffs[128];
// W in m16n8k16 fragment layout, fp16 hi/lo: [L][p][kc 8][nt 16][r 2][lane 32]
__device__ uint32_t g_Bfrag16[LL][2][8][16][2][32];

// ---------------- helpers ----------------
__device__ __forceinline__ uint32_t smem_u32(const void* p) {
    uint32_t a;
    asm("{ .reg .u64 t; cvta.to.shared.u64 t, %1; cvt.u32.u64 %0, t; }" : "=r"(a) : "l"(p));
    return a;
}
#define CP_ASYNC16(dst_u32, src_ptr) \
    asm volatile("cp.async.cg.shared.global [%0], [%1], 16;" :: "r"(dst_u32), "l"(src_ptr))
#define CP_COMMIT() asm volatile("cp.async.commit_group;")

__device__ __forceinline__ float warp_sum(float v) {
#pragma unroll
    for (int o = 16; o; o >>= 1) v += __shfl_xor_sync(0xffffffffu, v, o);
    return v;
}
__device__ __forceinline__ void fma4(float4& acc, float a, const float4& w) {
    acc.x = fmaf(a, w.x, acc.x);
    acc.y = fmaf(a, w.y, acc.y);
    acc.z = fmaf(a, w.z, acc.z);
    acc.w = fmaf(a, w.w, acc.w);
}
__device__ __forceinline__ void fma_h4(float4& acc, float w, uint2 u) {
    float2 f0 = __half22float2(*(__half2*)&u.x);
    float2 f1 = __half22float2(*(__half2*)&u.y);
    acc.x = fmaf(w, f0.x, acc.x);
    acc.y = fmaf(w, f0.y, acc.y);
    acc.z = fmaf(w, f1.x, acc.z);
    acc.w = fmaf(w, f1.y, acc.w);
}
__device__ __forceinline__ float4 h4_to_f4(uint2 u) {
    float2 f0 = __half22float2(*(__half2*)&u.x);
    float2 f1 = __half22float2(*(__half2*)&u.y);
    return make_float4(f0.x, f0.y, f1.x, f1.y);
}
__device__ __forceinline__ uint32_t pack_h2(float2 v) {
    __half2 h = __floats2half2_rn(v.x, v.y);
    return *(uint32_t*)&h;
}
__device__ __forceinline__ uint2 pack_h4(float4 v) {
    return make_uint2(pack_h2(make_float2(v.x, v.y)), pack_h2(make_float2(v.z, v.w)));
}
// fp16 hi/lo split of a float2 (W prep only)
__device__ __forceinline__ void split2(float2 v, uint32_t& hi, uint32_t& lo) {
    __half hx = __float2half_rn(v.x), hy = __float2half_rn(v.y);
    __half lx = __float2half_rn(v.x - __half2float(hx));
    __half ly = __float2half_rn(v.y - __half2float(hy));
    __half2 h2 = __halves2half2(hx, hy);
    __half2 l2 = __halves2half2(lx, ly);
    hi = *(uint32_t*)&h2;
    lo = *(uint32_t*)&l2;
}
__device__ __forceinline__ void mma_f16(float* d, uint32_t a0, uint32_t a1,
                                        uint32_t a2, uint32_t a3,
                                        uint32_t b0, uint32_t b1) {
    asm("mma.sync.aligned.m16n8k16.row.col.f32.f16.f16.f32 "
        "{%0,%1,%2,%3},{%4,%5,%6,%7},{%8,%9},{%0,%1,%2,%3};"
        : "+f"(d[0]), "+f"(d[1]), "+f"(d[2]), "+f"(d[3])
        : "r"(a0), "r"(a1), "r"(a2), "r"(a3), "r"(b0), "r"(b1));
}

// ---------------- mega kernel 1: embed + zero + W prep (independent work) ------
__global__ void __launch_bounds__(256) mega1_kernel(const float* __restrict__ x,
                                                    const float* __restrict__ We,
                                                    const float* __restrict__ be,
                                                    const float* __restrict__ Wgnn) {
    int blk = blockIdx.x;
    int tid = threadIdx.x;
    if (blk < EMB_BLOCKS) {
        // ---- embed: h = relu(x @ W_embed + b_embed), fp16 out
        __shared__ __align__(16) float sW[11 * HH];
        for (int i = tid; i < 11 * HH; i += 256) sW[i] = We[i];
        __syncthreads();
        int warp = tid >> 5, lane = tid & 31;
        int n = blk * 8 + warp;
        if (n >= NN) return;
        float xv = (lane < 11) ? x[(size_t)n * 11 + lane] : 0.f;
        float4 acc = ((const float4*)be)[lane];
        const float4* sWv = (const float4*)sW;
#pragma unroll
        for (int k = 0; k < 11; k++) {
            float a = __shfl_sync(0xffffffffu, xv, k);
            fma4(acc, a, sWv[k * 32 + lane]);
        }
        acc.x = fmaxf(acc.x, 0.f); acc.y = fmaxf(acc.y, 0.f);
        acc.z = fmaxf(acc.z, 0.f); acc.w = fmaxf(acc.w, 0.f);
        ((uint2*)g_h)[(size_t)n * 32 + lane] = pack_h4(acc);
    } else if (blk < EMB_BLOCKS + ZERO_BLOCKS) {
        int i = (blk - EMB_BLOCKS) * 256 + tid;
        if (i < NN) { g_deg[i] = 0; g_cursor[i] = 0; }
        if (i < GG) { g_gsum[i] = 0.f; g_gcnt[i] = 0.f; }
    } else {
        // ---- W prep: fp16 hi/lo split into m16n8k16 fragment layout
        int idx = (blk - EMB_BLOCKS - ZERO_BLOCKS) * 256 + tid;
        if (idx >= LL * 8 * 16 * 2 * 32) return;
        int lane = idx & 31;
        int r    = (idx >> 5) & 1;
        int nt   = (idx >> 6) & 15;
        int kc   = (idx >> 10) & 7;
        int l    = idx >> 13;
        int t = lane & 3, g = lane >> 2;
        int k0 = kc * 16 + r * 8 + 2 * t;
        int n  = nt * 8 + g;
        float w0 = Wgnn[(size_t)l * 16384 + k0 * 128 + n];
        float w1 = Wgnn[(size_t)l * 16384 + (k0 + 1) * 128 + n];
        uint32_t hi, lo;
        split2(make_float2(w0, w1), hi, lo);
        g_Bfrag16[l][0][kc][nt][r][lane] = hi;
        g_Bfrag16[l][1][kc][nt][r][lane] = lo;
    }
}

// ---------------- setup kernels ----------------
__global__ void count_kernel(const int* __restrict__ dst) {
    int e = blockIdx.x * blockDim.x + threadIdx.x;
    if (e < EE) atomicAdd(&g_deg[dst[e]], 1);
}

// scan1 + dis fused
__global__ void scan1_kernel() {
    __shared__ int sh[1024];
    int tid = threadIdx.x;
    int idx = blockIdx.x * 1024 + tid;
    int v = (idx < NN) ? g_deg[idx] : 0;
    if (idx < NN) g_dis[idx] = rsqrtf((float)(v + 1));   // +1 self loop
    sh[tid] = v;
    __syncthreads();
#pragma unroll
    for (int off = 1; off < 1024; off <<= 1) {
        int t = (tid >= off) ? sh[tid - off] : 0;
        __syncthreads();
        sh[tid] += t;
        __syncthreads();
    }
    if (idx < NN) g_rowptr[idx] = sh[tid] - v;
    if (tid == 1023) g_blocksums[blockIdx.x] = sh[1023];
}

__global__ void scan2_kernel(int nblocks) {
    __shared__ int sh[128];
    int tid = threadIdx.x;
    int v = (tid < nblocks) ? g_blocksums[tid] : 0;
    sh[tid] = v;
    __syncthreads();
#pragma unroll
    for (int off = 1; off < 128; off <<= 1) {
        int t = (tid >= off) ? sh[tid - off] : 0;
        __syncthreads();
        sh[tid] += t;
        __syncthreads();
    }
    if (tid < nblocks) g_blockoffs[tid] = sh[tid] - v;
    if (tid == 0) g_rowptr[NN] = EE;
}

__global__ void scan3_kernel() {
    int idx = blockIdx.x * 1024 + threadIdx.x;
    if (idx < NN) g_rowptr[idx] += g_blockoffs[blockIdx.x];
}

__global__ void fill_kernel(const int* __restrict__ src, const int* __restrict__ dst) {
    int e = blockIdx.x * blockDim.x + threadIdx.x;
    if (e >= EE) return;
    int s = src[e];
    int d = dst[e];
    int pos = g_rowptr[d] + atomicAdd(&g_cursor[d], 1);
    g_cw[pos] = make_uint2((unsigned)s, __float_as_uint(g_dis[s] * g_dis[d]));
}

// ---------------- mma.sync fp16 GEMM: g_m(half) = g_h(half) @ W ---------------
// 2-pass W hi/lo; cp.async double-buffered A and B chunks.
#define SA_STRIDE 12   // uints per row (8 + 4 pad)
__global__ void __launch_bounds__(256) gemm_mma_kernel(int layer) {
    __shared__ __align__(16) uint32_t sB[2][2][16][2][32];     // [buf][p][nt][r][lane] 16KB
    __shared__ __align__(16) uint32_t sA[2][128 * SA_STRIDE];  // 12KB

    int tid = threadIdx.x;
    int warp = tid >> 5, lane = tid & 31;
    int wm = warp >> 1;
    int wn = warp & 1;
    int g = lane >> 2, t = lane & 3;
    size_t rowbase = (size_t)blockIdx.x * 128;

    const char* hbase = (const char*)&g_h[rowbase * 64];   // 256 B per row
    const char* bsrc  = (const char*)&g_Bfrag16[layer][0][0][0][0][0];

    uint32_t sA_base = smem_u32(sA);
    uint32_t sB_base = smem_u32(sB);
    int r_ = tid >> 1, seg = tid & 1;

    float d[2][8][4];
#pragma unroll
    for (int mt = 0; mt < 2; mt++)
#pragma unroll
        for (int nt = 0; nt < 8; nt++)
#pragma unroll
            for (int j = 0; j < 4; j++) d[mt][nt][j] = 0.f;

    // issue chunk c into buffer c&1
    auto issue = [&](int c) {
        int buf = c & 1;
#pragma unroll
        for (int p = 0; p < 2; p++) {
            uint32_t dst = sB_base + buf * 8192 + p * 4096 + tid * 16;
            const char* src = bsrc + (size_t)p * 32768 + c * 4096 + tid * 16;
            CP_ASYNC16(dst, src);
        }
        uint32_t dstA = sA_base + buf * 6144 + (r_ * SA_STRIDE + seg * 4) * 4;
        const char* srcA = hbase + (size_t)r_ * 256 + c * 32 + seg * 16;
        CP_ASYNC16(dstA, srcA);
        CP_COMMIT();
    };

    issue(0);
    for (int c = 0; c < 8; c++) {
        if (c < 7) {
            issue(c + 1);
            asm volatile("cp.async.wait_group 1;");
        } else {
            asm volatile("cp.async.wait_group 0;");
        }
        __syncthreads();
        int buf = c & 1;

        uint32_t ah[2][4];
#pragma unroll
        for (int mt = 0; mt < 2; mt++) {
            int row = wm * 32 + mt * 16 + g;
            ah[mt][0] = sA[buf][row * SA_STRIDE + t];
            ah[mt][1] = sA[buf][(row + 8) * SA_STRIDE + t];
            ah[mt][2] = sA[buf][row * SA_STRIDE + 4 + t];
            ah[mt][3] = sA[buf][(row + 8) * SA_STRIDE + 4 + t];
        }
#pragma unroll
        for (int nt = 0; nt < 8; nt++) {
            int ntg = wn * 8 + nt;
            uint32_t bh0 = sB[buf][0][ntg][0][lane];
            uint32_t bh1 = sB[buf][0][ntg][1][lane];
            uint32_t bl0 = sB[buf][1][ntg][0][lane];
            uint32_t bl1 = sB[buf][1][ntg][1][lane];
#pragma unroll
            for (int mt = 0; mt < 2; mt++) {
                mma_f16(d[mt][nt], ah[mt][0], ah[mt][1], ah[mt][2], ah[mt][3], bh0, bh1);
                mma_f16(d[mt][nt], ah[mt][0], ah[mt][1], ah[mt][2], ah[mt][3], bl0, bl1);
            }
        }
        __syncthreads();
    }

#pragma unroll
    for (int mt = 0; mt < 2; mt++) {
        size_t row = rowbase + wm * 32 + mt * 16 + g;
#pragma unroll
        for (int nt = 0; nt < 8; nt++) {
            int colh = wn * 32 + nt * 4 + t;
            g_m[row * 64 + colh]       = __floats2half2_rn(d[mt][nt][0], d[mt][nt][1]);
            g_m[(row + 8) * 64 + colh] = __floats2half2_rn(d[mt][nt][2], d[mt][nt][3]);
        }
    }
}

// ---------------- fused aggregate + bias + LN + relu + residual ----------------
__global__ void __launch_bounds__(256) agg_kernel(const float* __restrict__ b,
                                                  const float* __restrict__ gam,
                                                  const float* __restrict__ bet) {
    int warp = threadIdx.x >> 5, lane = threadIdx.x & 31;
    int n = blockIdx.x * 8 + warp;
    if (n >= NN) return;

    const uint2* Mv = (const uint2*)g_m;   // 32 x uint2 per row (4 halves each)
    uint2* Hv = (uint2*)g_h;

    float dn = g_dis[n];
    float4 acc = make_float4(0.f, 0.f, 0.f, 0.f);
    fma_h4(acc, dn * dn, Mv[(size_t)n * 32 + lane]);   // self loop

    int beg = g_rowptr[n], end = g_rowptr[n + 1];
    int e = beg;
    for (; e + 4 <= end; e += 4) {
        uint2 c0 = g_cw[e],     c1 = g_cw[e + 1];
        uint2 c2 = g_cw[e + 2], c3 = g_cw[e + 3];
        uint2 u0 = Mv[(size_t)c0.x * 32 + lane];
        uint2 u1 = Mv[(size_t)c1.x * 32 + lane];
        uint2 u2 = Mv[(size_t)c2.x * 32 + lane];
        uint2 u3 = Mv[(size_t)c3.x * 32 + lane];
        fma_h4(acc, __uint_as_float(c0.y), u0);
        fma_h4(acc, __uint_as_float(c1.y), u1);
        fma_h4(acc, __uint_as_float(c2.y), u2);
        fma_h4(acc, __uint_as_float(c3.y), u3);
    }
    for (; e < end; e++) {
        uint2 cw = g_cw[e];
        fma_h4(acc, __uint_as_float(cw.y), Mv[(size_t)cw.x * 32 + lane]);
    }
    float4 bb = ((const float4*)b)[lane];
    acc.x += bb.x; acc.y += bb.y; acc.z += bb.z; acc.w += bb.w;

    float mu = warp_sum(acc.x + acc.y + acc.z + acc.w) * (1.f / 128.f);
    float4 dd = make_float4(acc.x - mu, acc.y - mu, acc.z - mu, acc.w - mu);
    float var = warp_sum(dd.x * dd.x + dd.y * dd.y + dd.z * dd.z + dd.w * dd.w) * (1.f / 128.f);
    float inv = rsqrtf(var + 1e-5f);

    float4 gg = ((const float4*)gam)[lane];
    float4 bt = ((const float4*)bet)[lane];
    float4 hv = h4_to_f4(Hv[(size_t)n * 32 + lane]);
    float4 o;
    o.x = fmaxf(dd.x * inv * gg.x + bt.x, 0.f) + hv.x;
    o.y = fmaxf(dd.y * inv * gg.y + bt.y, 0.f) + hv.y;
    o.z = fmaxf(dd.z * inv * gg.z + bt.z, 0.f) + hv.z;
    o.w = fmaxf(dd.w * inv * gg.w + bt.w, 0.f) + hv.w;
    Hv[(size_t)n * 32 + lane] = pack_h4(o);
}

// ---------------- pooling ----------------
__global__ void __launch_bounds__(256) pool_kernel(const int* __restrict__ batch,
                                                   const float* __restrict__ Wout) {
    int warp = threadIdx.x >> 5, lane = threadIdx.x & 31;
    int n = blockIdx.x * 8 + warp;
    if (n >= NN) return;
    float4 hv = h4_to_f4(((const uint2*)g_h)[(size_t)n * 32 + lane]);
    float4 wv = ((const float4*)Wout)[lane];
    float p = warp_sum(hv.x * wv.x + hv.y * wv.y + hv.z * wv.z + hv.w * wv.w);
    if (lane == 0) {
        int gidx = batch[n];
        atomicAdd(&g_gsum[gidx], p);
        atomicAdd(&g_gcnt[gidx], 1.f);
    }
}

__global__ void out_kernel(float* __restrict__ out, const float* __restrict__ bout) {
    int gidx = blockIdx.x * blockDim.x + threadIdx.x;
    if (gidx < GG)
        out[gidx] = g_gsum[gidx] / fmaxf(g_gcnt[gidx], 1.f) + bout[0];
}

// ---------------- launch ----------------
extern "C" void kernel_launch(void* const* d_in, const int* in_sizes, int n_in,
                              void* d_out, int out_size) {
    const float* x      = (const float*)d_in[0];
    const int*   eidx   = (const int*)d_in[1];    // int32 (JAX x64 disabled)
    const int*   batch  = (const int*)d_in[2];    // int32
    const float* Wemb   = (const float*)d_in[3];
    const float* bemb   = (const float*)d_in[4];
    const float* Wgnn   = (const float*)d_in[5];
    const float* bgnn   = (const float*)d_in[6];
    const float* gamma  = (const float*)d_in[7];
    const float* beta   = (const float*)d_in[8];
    const float* Wout   = (const float*)d_in[9];
    const float* bout   = (const float*)d_in[10];
    float* out = (float*)d_out;

    const int* src = eidx;
    const int* dst = eidx + EE;

    int nb_scan = (NN + 1023) / 1024;  // 98

    mega1_kernel<<<EMB_BLOCKS + ZERO_BLOCKS + PREP_BLOCKS, 256>>>(x, Wemb, bemb, Wgnn);
    count_kernel<<<(EE + 255) / 256, 256>>>(dst);
    scan1_kernel<<<nb_scan, 1024>>>();
    scan2_kernel<<<1, 128>>>(nb_scan);
    scan3_kernel<<<nb_scan, 1024>>>();
    fill_kernel<<<(EE + 255) / 256, 256>>>(src, dst);

    for (int l = 0; l < LL; l++) {
        gemm_mma_kernel<<<NT, 256>>>(l);
        agg_kernel<<<NN / 8, 256>>>(bgnn + l * HH, gamma + l * HH, beta + l * HH);
    }

    pool_kernel<<<NN / 8, 256>>>(batch, Wout);
    out_kernel<<<(GG + 255) / 256, 256>>>(out, bout);
}

// round 14
// speedup vs baseline: 1.5944x; 1.1014x over previous
#include <cuda_runtime.h>
#include <cuda_fp16.h>
#include <cstdint>

#define NN 100000
#define EE 1600000
#define GG 4096
#define HH 128
#define LL 4
#define NT 782                  // ceil(100000/128) row-tiles of 128
#define NPAD (NT * 128)         // 100096
#define NB_SCAN 98              // ceil(NN/1024)

#define EMB_BLOCKS 12500        // NN/8
#define ZERO_BLOCKS 391         // ceil(NN/256)
#define PREP_BLOCKS 128

// ---------------- device scratch (no allocations allowed) ----------------
__device__ int     g_deg[NN];
__device__ int     g_cursor[NN];
__device__ int     g_rowptr[NN + 1];
__device__ uint2   g_cw[EE];                 // (src idx, weight bits) fused
__device__ float   g_dis[NN];
__device__ __align__(16) __half2 g_h[(size_t)NPAD * 64];   // N x 128 fp16 residual (zero-init)
__device__ __align__(16) __half2 g_m[(size_t)NPAD * 64];   // N x 128 fp16 (padded)
__device__ float   g_gsum[GG];
__device__ float   g_gcnt[GG];
// decoupled-lookback scan state
__device__ volatile int g_agg_[NB_SCAN];
__device__ volatile int g_incl_[NB_SCAN];
__device__ volatile int g_flag_[NB_SCAN];    // 0=none, 1=agg, 2=inclusive
// W in m16n8k16 fragment layout, fp16 hi/lo: [L][p][kc 8][nt 16][r 2][lane 32]
__device__ uint32_t g_Bfrag16[LL][2][8][16][2][32];

// ---------------- helpers ----------------
__device__ __forceinline__ uint32_t smem_u32(const void* p) {
    uint32_t a;
    asm("{ .reg .u64 t; cvta.to.shared.u64 t, %1; cvt.u32.u64 %0, t; }" : "=r"(a) : "l"(p));
    return a;
}
#define CP_ASYNC16(dst_u32, src_ptr) \
    asm volatile("cp.async.cg.shared.global [%0], [%1], 16;" :: "r"(dst_u32), "l"(src_ptr))
#define CP_COMMIT() asm volatile("cp.async.commit_group;")

__device__ __forceinline__ float warp_sum(float v) {
#pragma unroll
    for (int o = 16; o; o >>= 1) v += __shfl_xor_sync(0xffffffffu, v, o);
    return v;
}
__device__ __forceinline__ int warp_sum_i(int v) {
#pragma unroll
    for (int o = 16; o; o >>= 1) v += __shfl_xor_sync(0xffffffffu, v, o);
    return v;
}
__device__ __forceinline__ void fma4(float4& acc, float a, const float4& w) {
    acc.x = fmaf(a, w.x, acc.x);
    acc.y = fmaf(a, w.y, acc.y);
    acc.z = fmaf(a, w.z, acc.z);
    acc.w = fmaf(a, w.w, acc.w);
}
__device__ __forceinline__ void fma_h4(float4& acc, float w, uint2 u) {
    float2 f0 = __half22float2(*(__half2*)&u.x);
    float2 f1 = __half22float2(*(__half2*)&u.y);
    acc.x = fmaf(w, f0.x, acc.x);
    acc.y = fmaf(w, f0.y, acc.y);
    acc.z = fmaf(w, f1.x, acc.z);
    acc.w = fmaf(w, f1.y, acc.w);
}
__device__ __forceinline__ float4 h4_to_f4(uint2 u) {
    float2 f0 = __half22float2(*(__half2*)&u.x);
    float2 f1 = __half22float2(*(__half2*)&u.y);
    return make_float4(f0.x, f0.y, f1.x, f1.y);
}
__device__ __forceinline__ uint32_t pack_h2(float2 v) {
    __half2 h = __floats2half2_rn(v.x, v.y);
    return *(uint32_t*)&h;
}
__device__ __forceinline__ uint2 pack_h4(float4 v) {
    return make_uint2(pack_h2(make_float2(v.x, v.y)), pack_h2(make_float2(v.z, v.w)));
}
// fp16 hi/lo split of a float2 (W prep only)
__device__ __forceinline__ void split2(float2 v, uint32_t& hi, uint32_t& lo) {
    __half hx = __float2half_rn(v.x), hy = __float2half_rn(v.y);
    __half lx = __float2half_rn(v.x - __half2float(hx));
    __half ly = __float2half_rn(v.y - __half2float(hy));
    __half2 h2 = __halves2half2(hx, hy);
    __half2 l2 = __halves2half2(lx, ly);
    hi = *(uint32_t*)&h2;
    lo = *(uint32_t*)&l2;
}
__device__ __forceinline__ void mma_f16(float* d, uint32_t a0, uint32_t a1,
                                        uint32_t a2, uint32_t a3,
                                        uint32_t b0, uint32_t b1) {
    asm("mma.sync.aligned.m16n8k16.row.col.f32.f16.f16.f32 "
        "{%0,%1,%2,%3},{%4,%5,%6,%7},{%8,%9},{%0,%1,%2,%3};"
        : "+f"(d[0]), "+f"(d[1]), "+f"(d[2]), "+f"(d[3])
        : "r"(a0), "r"(a1), "r"(a2), "r"(a3), "r"(b0), "r"(b1));
}

// ---------------- mega kernel 1: embed + zero + W prep (independent work) ------
__global__ void __launch_bounds__(256) mega1_kernel(const float* __restrict__ x,
                                                    const float* __restrict__ We,
                                                    const float* __restrict__ be,
                                                    const float* __restrict__ Wgnn) {
    int blk = blockIdx.x;
    int tid = threadIdx.x;
    if (blk < EMB_BLOCKS) {
        // ---- embed: h = relu(x @ W_embed + b_embed), fp16 out
        __shared__ __align__(16) float sW[11 * HH];
        for (int i = tid; i < 11 * HH; i += 256) sW[i] = We[i];
        __syncthreads();
        int warp = tid >> 5, lane = tid & 31;
        int n = blk * 8 + warp;
        if (n >= NN) return;
        float xv = (lane < 11) ? x[(size_t)n * 11 + lane] : 0.f;
        float4 acc = ((const float4*)be)[lane];
        const float4* sWv = (const float4*)sW;
#pragma unroll
        for (int k = 0; k < 11; k++) {
            float a = __shfl_sync(0xffffffffu, xv, k);
            fma4(acc, a, sWv[k * 32 + lane]);
        }
        acc.x = fmaxf(acc.x, 0.f); acc.y = fmaxf(acc.y, 0.f);
        acc.z = fmaxf(acc.z, 0.f); acc.w = fmaxf(acc.w, 0.f);
        ((uint2*)g_h)[(size_t)n * 32 + lane] = pack_h4(acc);
    } else if (blk < EMB_BLOCKS + ZERO_BLOCKS) {
        int i = (blk - EMB_BLOCKS) * 256 + tid;
        if (i < NN) { g_deg[i] = 0; g_cursor[i] = 0; }
        if (i < GG) { g_gsum[i] = 0.f; g_gcnt[i] = 0.f; }
        if (i < NB_SCAN) g_flag_[i] = 0;
    } else {
        // ---- W prep: fp16 hi/lo split into m16n8k16 fragment layout
        int idx = (blk - EMB_BLOCKS - ZERO_BLOCKS) * 256 + tid;
        if (idx >= LL * 8 * 16 * 2 * 32) return;
        int lane = idx & 31;
        int r    = (idx >> 5) & 1;
        int nt   = (idx >> 6) & 15;
        int kc   = (idx >> 10) & 7;
        int l    = idx >> 13;
        int t = lane & 3, g = lane >> 2;
        int k0 = kc * 16 + r * 8 + 2 * t;
        int n  = nt * 8 + g;
        float w0 = Wgnn[(size_t)l * 16384 + k0 * 128 + n];
        float w1 = Wgnn[(size_t)l * 16384 + (k0 + 1) * 128 + n];
        uint32_t hi, lo;
        split2(make_float2(w0, w1), hi, lo);
        g_Bfrag16[l][0][kc][nt][r][lane] = hi;
        g_Bfrag16[l][1][kc][nt][r][lane] = lo;
    }
}

// ---------------- setup kernels ----------------
__global__ void count_kernel(const int* __restrict__ dst) {
    int e = blockIdx.x * blockDim.x + threadIdx.x;
    if (e < EE) atomicAdd(&g_deg[dst[e]], 1);
}

// single-pass decoupled-lookback exclusive scan (+ dis); 98 blocks all resident
__global__ void __launch_bounds__(1024) scan_kernel() {
    __shared__ int sh[1024];
    __shared__ int s_prefix;
    int b = blockIdx.x, tid = threadIdx.x;
    int idx = b * 1024 + tid;
    int v = (idx < NN) ? g_deg[idx] : 0;
    if (idx < NN) g_dis[idx] = rsqrtf((float)(v + 1));   // +1 self loop
    sh[tid] = v;
    __syncthreads();
#pragma unroll
    for (int off = 1; off < 1024; off <<= 1) {
        int t = (tid >= off) ? sh[tid - off] : 0;
        __syncthreads();
        sh[tid] += t;
        __syncthreads();
    }
    int total = sh[1023];
    if (tid == 0) {
        g_agg_[b] = total;
        __threadfence();
        if (b == 0) {
            g_incl_[0] = total;
            __threadfence();
            g_flag_[0] = 2;
            s_prefix = 0;
        } else {
            g_flag_[b] = 1;
        }
    }
    if (b > 0 && tid < 32) {
        int prefix = 0;
        int i = b - 1;
        while (true) {
            int j = i - tid;
            int f = (j >= 0) ? g_flag_[j] : 2;
            while (__any_sync(0xffffffffu, (j >= 0) && f == 0))
                f = (j >= 0) ? g_flag_[j] : 2;
            unsigned mask2 = __ballot_sync(0xffffffffu, (j >= 0) && f == 2);
            int stop_lane = mask2 ? (__ffs(mask2) - 1) : 32;
            int contrib = 0;
            if (j >= 0 && tid <= stop_lane)
                contrib = (tid == stop_lane) ? g_incl_[j] : g_agg_[j];
            prefix += warp_sum_i((tid <= stop_lane) ? contrib : 0);
            if (stop_lane < 32) break;
            i -= 32;
        }
        if (tid == 0) {
            g_incl_[b] = prefix + total;
            __threadfence();
            g_flag_[b] = 2;
            s_prefix = prefix;
        }
    }
    __syncthreads();
    int prefix = s_prefix;
    if (idx < NN) g_rowptr[idx] = prefix + sh[tid] - v;  // exclusive
    if (b == NB_SCAN - 1 && tid == 0) g_rowptr[NN] = EE;
}

__global__ void fill_kernel(const int* __restrict__ src, const int* __restrict__ dst) {
    int e = blockIdx.x * blockDim.x + threadIdx.x;
    if (e >= EE) return;
    int s = src[e];
    int d = dst[e];
    int pos = g_rowptr[d] + atomicAdd(&g_cursor[d], 1);
    g_cw[pos] = make_uint2((unsigned)s, __float_as_uint(g_dis[s] * g_dis[d]));
}

// ---------------- mma.sync fp16 GEMM: g_m(half) = g_h(half) @ W ---------------
// 2-pass W hi/lo; 3-stage cp.async ring, ONE syncthreads per K-chunk.
#define SA_STRIDE 12   // uints per row (8 + 4 pad)
__global__ void __launch_bounds__(256) gemm_mma_kernel(int layer) {
    __shared__ __align__(16) uint32_t sB[3][2][16][2][32];     // [buf][p][nt][r][lane] 24KB
    __shared__ __align__(16) uint32_t sA[3][128 * SA_STRIDE];  // 18KB

    int tid = threadIdx.x;
    int warp = tid >> 5, lane = tid & 31;
    int wm = warp >> 1;
    int wn = warp & 1;
    int g = lane >> 2, t = lane & 3;
    size_t rowbase = (size_t)blockIdx.x * 128;

    const char* hbase = (const char*)&g_h[rowbase * 64];   // 256 B per row
    const char* bsrc  = (const char*)&g_Bfrag16[layer][0][0][0][0][0];

    uint32_t sA_base = smem_u32(sA);
    uint32_t sB_base = smem_u32(sB);
    int r_ = tid >> 1, seg = tid & 1;

    float d[2][8][4];
#pragma unroll
    for (int mt = 0; mt < 2; mt++)
#pragma unroll
        for (int nt = 0; nt < 8; nt++)
#pragma unroll
            for (int j = 0; j < 4; j++) d[mt][nt][j] = 0.f;

    auto issue = [&](int c) {
        int buf = c % 3;
#pragma unroll
        for (int p = 0; p < 2; p++) {
            uint32_t dst = sB_base + buf * 8192 + p * 4096 + tid * 16;
            const char* src = bsrc + (size_t)p * 32768 + c * 4096 + tid * 16;
            CP_ASYNC16(dst, src);
        }
        uint32_t dstA = sA_base + buf * 6144 + (r_ * SA_STRIDE + seg * 4) * 4;
        const char* srcA = hbase + (size_t)r_ * 256 + c * 32 + seg * 16;
        CP_ASYNC16(dstA, srcA);
        CP_COMMIT();
    };

    issue(0);
    issue(1);
    for (int c = 0; c < 8; c++) {
        // require group c complete; outstanding allowed = issued - (c+1)
        if (c < 7) asm volatile("cp.async.wait_group 1;");
        else       asm volatile("cp.async.wait_group 0;");
        __syncthreads();   // data visible to all; all warps past compute c-1
        int buf = c % 3;

        uint32_t ah[2][4];
#pragma unroll
        for (int mt = 0; mt < 2; mt++) {
            int row = wm * 32 + mt * 16 + g;
            ah[mt][0] = sA[buf][row * SA_STRIDE + t];
            ah[mt][1] = sA[buf][(row + 8) * SA_STRIDE + t];
            ah[mt][2] = sA[buf][row * SA_STRIDE + 4 + t];
            ah[mt][3] = sA[buf][(row + 8) * SA_STRIDE + 4 + t];
        }
#pragma unroll
        for (int nt = 0; nt < 8; nt++) {
            int ntg = wn * 8 + nt;
            uint32_t bh0 = sB[buf][0][ntg][0][lane];
            uint32_t bh1 = sB[buf][0][ntg][1][lane];
            uint32_t bl0 = sB[buf][1][ntg][0][lane];
            uint32_t bl1 = sB[buf][1][ntg][1][lane];
#pragma unroll
            for (int mt = 0; mt < 2; mt++) {
                mma_f16(d[mt][nt], ah[mt][0], ah[mt][1], ah[mt][2], ah[mt][3], bh0, bh1);
                mma_f16(d[mt][nt], ah[mt][0], ah[mt][1], ah[mt][2], ah[mt][3], bl0, bl1);
            }
        }
        if (c + 2 < 8) issue(c + 2);   // refills buf (c+2)%3 = (c-1)%3, safe post-sync
    }

#pragma unroll
    for (int mt = 0; mt < 2; mt++) {
        size_t row = rowbase + wm * 32 + mt * 16 + g;
#pragma unroll
        for (int nt = 0; nt < 8; nt++) {
            int colh = wn * 32 + nt * 4 + t;
            g_m[row * 64 + colh]       = __floats2half2_rn(d[mt][nt][0], d[mt][nt][1]);
            g_m[(row + 8) * 64 + colh] = __floats2half2_rn(d[mt][nt][2], d[mt][nt][3]);
        }
    }
}

// ------- fused aggregate + bias + LN + relu + residual (+ pool on last layer) ---
__global__ void __launch_bounds__(256) agg_kernel(const float* __restrict__ b,
                                                  const float* __restrict__ gam,
                                                  const float* __restrict__ bet,
                                                  const int* __restrict__ batch,
                                                  const float* __restrict__ Wout,
                                                  int last) {
    int warp = threadIdx.x >> 5, lane = threadIdx.x & 31;
    int n = blockIdx.x * 8 + warp;
    if (n >= NN) return;

    const uint2* Mv = (const uint2*)g_m;   // 32 x uint2 per row (4 halves each)
    uint2* Hv = (uint2*)g_h;

    float dn = g_dis[n];
    float4 acc = make_float4(0.f, 0.f, 0.f, 0.f);
    fma_h4(acc, dn * dn, Mv[(size_t)n * 32 + lane]);   // self loop

    int beg = g_rowptr[n], end = g_rowptr[n + 1];
    int e = beg;
    for (; e + 4 <= end; e += 4) {
        uint2 c0 = g_cw[e],     c1 = g_cw[e + 1];
        uint2 c2 = g_cw[e + 2], c3 = g_cw[e + 3];
        uint2 u0 = Mv[(size_t)c0.x * 32 + lane];
        uint2 u1 = Mv[(size_t)c1.x * 32 + lane];
        uint2 u2 = Mv[(size_t)c2.x * 32 + lane];
        uint2 u3 = Mv[(size_t)c3.x * 32 + lane];
        fma_h4(acc, __uint_as_float(c0.y), u0);
        fma_h4(acc, __uint_as_float(c1.y), u1);
        fma_h4(acc, __uint_as_float(c2.y), u2);
        fma_h4(acc, __uint_as_float(c3.y), u3);
    }
    for (; e < end; e++) {
        uint2 cw = g_cw[e];
        fma_h4(acc, __uint_as_float(cw.y), Mv[(size_t)cw.x * 32 + lane]);
    }
    float4 bb = ((const float4*)b)[lane];
    acc.x += bb.x; acc.y += bb.y; acc.z += bb.z; acc.w += bb.w;

    float mu = warp_sum(acc.x + acc.y + acc.z + acc.w) * (1.f / 128.f);
    float4 dd = make_float4(acc.x - mu, acc.y - mu, acc.z - mu, acc.w - mu);
    float var = warp_sum(dd.x * dd.x + dd.y * dd.y + dd.z * dd.z + dd.w * dd.w) * (1.f / 128.f);
    float inv = rsqrtf(var + 1e-5f);

    float4 gg = ((const float4*)gam)[lane];
    float4 bt = ((const float4*)bet)[lane];
    float4 hv = h4_to_f4(Hv[(size_t)n * 32 + lane]);
    float4 o;
    o.x = fmaxf(dd.x * inv * gg.x + bt.x, 0.f) + hv.x;
    o.y = fmaxf(dd.y * inv * gg.y + bt.y, 0.f) + hv.y;
    o.z = fmaxf(dd.z * inv * gg.z + bt.z, 0.f) + hv.z;
    o.w = fmaxf(dd.w * inv * gg.w + bt.w, 0.f) + hv.w;

    if (!last) {
        Hv[(size_t)n * 32 + lane] = pack_h4(o);
    } else {
        // fused global-mean-pool contribution (h never re-read)
        float4 wv = ((const float4*)Wout)[lane];
        float p = warp_sum(o.x * wv.x + o.y * wv.y + o.z * wv.z + o.w * wv.w);
        if (lane == 0) {
            int gidx = batch[n];
            atomicAdd(&g_gsum[gidx], p);
            atomicAdd(&g_gcnt[gidx], 1.f);
        }
    }
}

__global__ void out_kernel(float* __restrict__ out, const float* __restrict__ bout) {
    int gidx = blockIdx.x * blockDim.x + threadIdx.x;
    if (gidx < GG)
        out[gidx] = g_gsum[gidx] / fmaxf(g_gcnt[gidx], 1.f) + bout[0];
}

// ---------------- launch ----------------
extern "C" void kernel_launch(void* const* d_in, const int* in_sizes, int n_in,
                              void* d_out, int out_size) {
    const float* x      = (const float*)d_in[0];
    const int*   eidx   = (const int*)d_in[1];    // int32 (JAX x64 disabled)
    const int*   batch  = (const int*)d_in[2];    // int32
    const float* Wemb   = (const float*)d_in[3];
    const float* bemb   = (const float*)d_in[4];
    const float* Wgnn   = (const float*)d_in[5];
    const float* bgnn   = (const float*)d_in[6];
    const float* gamma  = (const float*)d_in[7];
    const float* beta   = (const float*)d_in[8];
    const float* Wout   = (const float*)d_in[9];
    const float* bout   = (const float*)d_in[10];
    float* out = (float*)d_out;

    const int* src = eidx;
    const int* dst = eidx + EE;

    mega1_kernel<<<EMB_BLOCKS + ZERO_BLOCKS + PREP_BLOCKS, 256>>>(x, Wemb, bemb, Wgnn);
    count_kernel<<<(EE + 255) / 256, 256>>>(dst);
    scan_kernel<<<NB_SCAN, 1024>>>();
    fill_kernel<<<(EE + 255) / 256, 256>>>(src, dst);

    for (int l = 0; l < LL; l++) {
        gemm_mma_kernel<<<NT, 256>>>(l);
        agg_kernel<<<NN / 8, 256>>>(bgnn + l * HH, gamma + l * HH, beta + l * HH,
                                    batch, Wout, l == LL - 1);
    }

    out_kernel<<<(GG + 255) / 256, 256>>>(out, bout);
}

// round 15
// speedup vs baseline: 1.5956x; 1.0007x over previous
#include <cuda_runtime.h>
#include <cuda_fp16.h>
#include <cstdint>

#define NN 100000
#define EE 1600000
#define GG 4096
#define HH 128
#define LL 4
#define NT 782                  // ceil(100000/128) row-tiles of 128
#define NPAD (NT * 128)         // 100096
#define NB_SCAN 98              // ceil(NN/1024)

#define EMB_BLOCKS 12500        // NN/8
#define ZERO_BLOCKS 391         // ceil(NN/256)
#define PREP_BLOCKS 128

// ---------------- device scratch (no allocations allowed) ----------------
__device__ int     g_deg[NN];
__device__ int     g_rowptr[NN + 1];
__device__ int     g_rank[EE];               // within-row rank of each edge
__device__ uint2   g_cw[EE];                 // (src idx, weight bits) fused
__device__ float   g_dis[NN];
__device__ __align__(16) __half2 g_h[(size_t)NPAD * 64];   // N x 128 fp16 residual (zero-init)
__device__ __align__(16) __half2 g_m[(size_t)NPAD * 64];   // N x 128 fp16 (padded)
__device__ float   g_gsum[GG];
__device__ float   g_gcnt[GG];
// decoupled-lookback scan state
__device__ volatile int g_agg_[NB_SCAN];
__device__ volatile int g_incl_[NB_SCAN];
__device__ volatile int g_flag_[NB_SCAN];    // 0=none, 1=agg, 2=inclusive
// W in m16n8k16 fragment layout, fp16 hi/lo: [L][p][kc 8][nt 16][r 2][lane 32]
__device__ uint32_t g_Bfrag16[LL][2][8][16][2][32];

// ---------------- helpers ----------------
__device__ __forceinline__ uint32_t smem_u32(const void* p) {
    uint32_t a;
    asm("{ .reg .u64 t; cvta.to.shared.u64 t, %1; cvt.u32.u64 %0, t; }" : "=r"(a) : "l"(p));
    return a;
}
#define CP_ASYNC16(dst_u32, src_ptr) \
    asm volatile("cp.async.cg.shared.global [%0], [%1], 16;" :: "r"(dst_u32), "l"(src_ptr))
#define CP_COMMIT() asm volatile("cp.async.commit_group;")

__device__ __forceinline__ float warp_sum(float v) {
#pragma unroll
    for (int o = 16; o; o >>= 1) v += __shfl_xor_sync(0xffffffffu, v, o);
    return v;
}
__device__ __forceinline__ int warp_sum_i(int v) {
#pragma unroll
    for (int o = 16; o; o >>= 1) v += __shfl_xor_sync(0xffffffffu, v, o);
    return v;
}
__device__ __forceinline__ void fma4(float4& acc, float a, const float4& w) {
    acc.x = fmaf(a, w.x, acc.x);
    acc.y = fmaf(a, w.y, acc.y);
    acc.z = fmaf(a, w.z, acc.z);
    acc.w = fmaf(a, w.w, acc.w);
}
__device__ __forceinline__ void fma_h4(float4& acc, float w, uint2 u) {
    float2 f0 = __half22float2(*(__half2*)&u.x);
    float2 f1 = __half22float2(*(__half2*)&u.y);
    acc.x = fmaf(w, f0.x, acc.x);
    acc.y = fmaf(w, f0.y, acc.y);
    acc.z = fmaf(w, f1.x, acc.z);
    acc.w = fmaf(w, f1.y, acc.w);
}
__device__ __forceinline__ float4 h4_to_f4(uint2 u) {
    float2 f0 = __half22float2(*(__half2*)&u.x);
    float2 f1 = __half22float2(*(__half2*)&u.y);
    return make_float4(f0.x, f0.y, f1.x, f1.y);
}
__device__ __forceinline__ uint32_t pack_h2(float2 v) {
    __half2 h = __floats2half2_rn(v.x, v.y);
    return *(uint32_t*)&h;
}
__device__ __forceinline__ uint2 pack_h4(float4 v) {
    return make_uint2(pack_h2(make_float2(v.x, v.y)), pack_h2(make_float2(v.z, v.w)));
}
// fp16 hi/lo split of a float2 (W prep only)
__device__ __forceinline__ void split2(float2 v, uint32_t& hi, uint32_t& lo) {
    __half hx = __float2half_rn(v.x), hy = __float2half_rn(v.y);
    __half lx = __float2half_rn(v.x - __half2float(hx));
    __half ly = __float2half_rn(v.y - __half2float(hy));
    __half2 h2 = __halves2half2(hx, hy);
    __half2 l2 = __halves2half2(lx, ly);
    hi = *(uint32_t*)&h2;
    lo = *(uint32_t*)&l2;
}
__device__ __forceinline__ void mma_f16(float* d, uint32_t a0, uint32_t a1,
                                        uint32_t a2, uint32_t a3,
                                        uint32_t b0, uint32_t b1) {
    asm("mma.sync.aligned.m16n8k16.row.col.f32.f16.f16.f32 "
        "{%0,%1,%2,%3},{%4,%5,%6,%7},{%8,%9},{%0,%1,%2,%3};"
        : "+f"(d[0]), "+f"(d[1]), "+f"(d[2]), "+f"(d[3])
        : "r"(a0), "r"(a1), "r"(a2), "r"(a3), "r"(b0), "r"(b1));
}

// ---------------- mega kernel 1: embed + zero + W prep (independent work) ------
__global__ void __launch_bounds__(256) mega1_kernel(const float* __restrict__ x,
                                                    const float* __restrict__ We,
                                                    const float* __restrict__ be,
                                                    const float* __restrict__ Wgnn) {
    int blk = blockIdx.x;
    int tid = threadIdx.x;
    if (blk < EMB_BLOCKS) {
        // ---- embed: h = relu(x @ W_embed + b_embed), fp16 out
        __shared__ __align__(16) float sW[11 * HH];
        for (int i = tid; i < 11 * HH; i += 256) sW[i] = We[i];
        __syncthreads();
        int warp = tid >> 5, lane = tid & 31;
        int n = blk * 8 + warp;
        if (n >= NN) return;
        float xv = (lane < 11) ? x[(size_t)n * 11 + lane] : 0.f;
        float4 acc = ((const float4*)be)[lane];
        const float4* sWv = (const float4*)sW;
#pragma unroll
        for (int k = 0; k < 11; k++) {
            float a = __shfl_sync(0xffffffffu, xv, k);
            fma4(acc, a, sWv[k * 32 + lane]);
        }
        acc.x = fmaxf(acc.x, 0.f); acc.y = fmaxf(acc.y, 0.f);
        acc.z = fmaxf(acc.z, 0.f); acc.w = fmaxf(acc.w, 0.f);
        ((uint2*)g_h)[(size_t)n * 32 + lane] = pack_h4(acc);
    } else if (blk < EMB_BLOCKS + ZERO_BLOCKS) {
        int i = (blk - EMB_BLOCKS) * 256 + tid;
        if (i < NN) g_deg[i] = 0;
        if (i < GG) { g_gsum[i] = 0.f; g_gcnt[i] = 0.f; }
        if (i < NB_SCAN) g_flag_[i] = 0;
    } else {
        // ---- W prep: fp16 hi/lo split into m16n8k16 fragment layout
        int idx = (blk - EMB_BLOCKS - ZERO_BLOCKS) * 256 + tid;
        if (idx >= LL * 8 * 16 * 2 * 32) return;
        int lane = idx & 31;
        int r    = (idx >> 5) & 1;
        int nt   = (idx >> 6) & 15;
        int kc   = (idx >> 10) & 7;
        int l    = idx >> 13;
        int t = lane & 3, g = lane >> 2;
        int k0 = kc * 16 + r * 8 + 2 * t;
        int n  = nt * 8 + g;
        float w0 = Wgnn[(size_t)l * 16384 + k0 * 128 + n];
        float w1 = Wgnn[(size_t)l * 16384 + (k0 + 1) * 128 + n];
        uint32_t hi, lo;
        split2(make_float2(w0, w1), hi, lo);
        g_Bfrag16[l][0][kc][nt][r][lane] = hi;
        g_Bfrag16[l][1][kc][nt][r][lane] = lo;
    }
}

// ---------------- count: degree + per-edge rank (4 edges/thread) ---------------
__global__ void __launch_bounds__(256) count_kernel(const int* __restrict__ dst) {
    int e4 = (blockIdx.x * blockDim.x + threadIdx.x) * 4;
    if (e4 >= EE) return;
    int4 d = *(const int4*)(dst + e4);
    int r0 = atomicAdd(&g_deg[d.x], 1);
    int r1 = atomicAdd(&g_deg[d.y], 1);
    int r2 = atomicAdd(&g_deg[d.z], 1);
    int r3 = atomicAdd(&g_deg[d.w], 1);
    *(int4*)(g_rank + e4) = make_int4(r0, r1, r2, r3);
}

// single-pass decoupled-lookback exclusive scan (+ dis); 98 blocks all resident
__global__ void __launch_bounds__(1024) scan_kernel() {
    __shared__ int sh[1024];
    __shared__ int s_prefix;
    int b = blockIdx.x, tid = threadIdx.x;
    int idx = b * 1024 + tid;
    int v = (idx < NN) ? g_deg[idx] : 0;
    if (idx < NN) g_dis[idx] = rsqrtf((float)(v + 1));   // +1 self loop
    sh[tid] = v;
    __syncthreads();
#pragma unroll
    for (int off = 1; off < 1024; off <<= 1) {
        int t = (tid >= off) ? sh[tid - off] : 0;
        __syncthreads();
        sh[tid] += t;
        __syncthreads();
    }
    int total = sh[1023];
    if (tid == 0) {
        g_agg_[b] = total;
        __threadfence();
        if (b == 0) {
            g_incl_[0] = total;
            __threadfence();
            g_flag_[0] = 2;
            s_prefix = 0;
        } else {
            g_flag_[b] = 1;
        }
    }
    if (b > 0 && tid < 32) {
        int prefix = 0;
        int i = b - 1;
        while (true) {
            int j = i - tid;
            int f = (j >= 0) ? g_flag_[j] : 2;
            while (__any_sync(0xffffffffu, (j >= 0) && f == 0))
                f = (j >= 0) ? g_flag_[j] : 2;
            unsigned mask2 = __ballot_sync(0xffffffffu, (j >= 0) && f == 2);
            int stop_lane = mask2 ? (__ffs(mask2) - 1) : 32;
            int contrib = 0;
            if (j >= 0 && tid <= stop_lane)
                contrib = (tid == stop_lane) ? g_incl_[j] : g_agg_[j];
            prefix += warp_sum_i((tid <= stop_lane) ? contrib : 0);
            if (stop_lane < 32) break;
            i -= 32;
        }
        if (tid == 0) {
            g_incl_[b] = prefix + total;
            __threadfence();
            g_flag_[b] = 2;
            s_prefix = prefix;
        }
    }
    __syncthreads();
    int prefix = s_prefix;
    if (idx < NN) g_rowptr[idx] = prefix + sh[tid] - v;  // exclusive
    if (b == NB_SCAN - 1 && tid == 0) g_rowptr[NN] = EE;
}

// ---------------- fill: atomic-free scatter (4 edges/thread) -------------------
__global__ void __launch_bounds__(256) fill_kernel(const int* __restrict__ src,
                                                   const int* __restrict__ dst) {
    int e4 = (blockIdx.x * blockDim.x + threadIdx.x) * 4;
    if (e4 >= EE) return;
    int4 s = *(const int4*)(src + e4);
    int4 d = *(const int4*)(dst + e4);
    int4 r = *(const int4*)(g_rank + e4);
    float ds0 = g_dis[s.x], ds1 = g_dis[s.y], ds2 = g_dis[s.z], ds3 = g_dis[s.w];
    float dd0 = g_dis[d.x], dd1 = g_dis[d.y], dd2 = g_dis[d.z], dd3 = g_dis[d.w];
    int p0 = g_rowptr[d.x] + r.x;
    int p1 = g_rowptr[d.y] + r.y;
    int p2 = g_rowptr[d.z] + r.z;
    int p3 = g_rowptr[d.w] + r.w;
    g_cw[p0] = make_uint2((unsigned)s.x, __float_as_uint(ds0 * dd0));
    g_cw[p1] = make_uint2((unsigned)s.y, __float_as_uint(ds1 * dd1));
    g_cw[p2] = make_uint2((unsigned)s.z, __float_as_uint(ds2 * dd2));
    g_cw[p3] = make_uint2((unsigned)s.w, __float_as_uint(ds3 * dd3));
}

// ---------------- mma.sync fp16 GEMM: g_m(half) = g_h(half) @ W ---------------
// 2-pass W hi/lo; 3-stage cp.async ring, ONE syncthreads per K-chunk.
#define SA_STRIDE 12   // uints per row (8 + 4 pad)
__global__ void __launch_bounds__(256) gemm_mma_kernel(int layer) {
    __shared__ __align__(16) uint32_t sB[3][2][16][2][32];     // [buf][p][nt][r][lane] 24KB
    __shared__ __align__(16) uint32_t sA[3][128 * SA_STRIDE];  // 18KB

    int tid = threadIdx.x;
    int warp = tid >> 5, lane = tid & 31;
    int wm = warp >> 1;
    int wn = warp & 1;
    int g = lane >> 2, t = lane & 3;
    size_t rowbase = (size_t)blockIdx.x * 128;

    const char* hbase = (const char*)&g_h[rowbase * 64];   // 256 B per row
    const char* bsrc  = (const char*)&g_Bfrag16[layer][0][0][0][0][0];

    uint32_t sA_base = smem_u32(sA);
    uint32_t sB_base = smem_u32(sB);
    int r_ = tid >> 1, seg = tid & 1;

    float d[2][8][4];
#pragma unroll
    for (int mt = 0; mt < 2; mt++)
#pragma unroll
        for (int nt = 0; nt < 8; nt++)
#pragma unroll
            for (int j = 0; j < 4; j++) d[mt][nt][j] = 0.f;

    auto issue = [&](int c) {
        int buf = c % 3;
#pragma unroll
        for (int p = 0; p < 2; p++) {
            uint32_t dst = sB_base + buf * 8192 + p * 4096 + tid * 16;
            const char* src = bsrc + (size_t)p * 32768 + c * 4096 + tid * 16;
            CP_ASYNC16(dst, src);
        }
        uint32_t dstA = sA_base + buf * 6144 + (r_ * SA_STRIDE + seg * 4) * 4;
        const char* srcA = hbase + (size_t)r_ * 256 + c * 32 + seg * 16;
        CP_ASYNC16(dstA, srcA);
        CP_COMMIT();
    };

    issue(0);
    issue(1);
    for (int c = 0; c < 8; c++) {
        if (c < 7) asm volatile("cp.async.wait_group 1;");
        else       asm volatile("cp.async.wait_group 0;");
        __syncthreads();
        int buf = c % 3;

        uint32_t ah[2][4];
#pragma unroll
        for (int mt = 0; mt < 2; mt++) {
            int row = wm * 32 + mt * 16 + g;
            ah[mt][0] = sA[buf][row * SA_STRIDE + t];
            ah[mt][1] = sA[buf][(row + 8) * SA_STRIDE + t];
            ah[mt][2] = sA[buf][row * SA_STRIDE + 4 + t];
            ah[mt][3] = sA[buf][(row + 8) * SA_STRIDE + 4 + t];
        }
#pragma unroll
        for (int nt = 0; nt < 8; nt++) {
            int ntg = wn * 8 + nt;
            uint32_t bh0 = sB[buf][0][ntg][0][lane];
            uint32_t bh1 = sB[buf][0][ntg][1][lane];
            uint32_t bl0 = sB[buf][1][ntg][0][lane];
            uint32_t bl1 = sB[buf][1][ntg][1][lane];
#pragma unroll
            for (int mt = 0; mt < 2; mt++) {
                mma_f16(d[mt][nt], ah[mt][0], ah[mt][1], ah[mt][2], ah[mt][3], bh0, bh1);
                mma_f16(d[mt][nt], ah[mt][0], ah[mt][1], ah[mt][2], ah[mt][3], bl0, bl1);
            }
        }
        if (c + 2 < 8) issue(c + 2);
    }

#pragma unroll
    for (int mt = 0; mt < 2; mt++) {
        size_t row = rowbase + wm * 32 + mt * 16 + g;
#pragma unroll
        for (int nt = 0; nt < 8; nt++) {
            int colh = wn * 32 + nt * 4 + t;
            g_m[row * 64 + colh]       = __floats2half2_rn(d[mt][nt][0], d[mt][nt][1]);
            g_m[(row + 8) * 64 + colh] = __floats2half2_rn(d[mt][nt][2], d[mt][nt][3]);
        }
    }
}

// ------- fused aggregate + bias + LN + relu + residual (+ pool on last layer) ---
__global__ void __launch_bounds__(256) agg_kernel(const float* __restrict__ b,
                                                  const float* __restrict__ gam,
                                                  const float* __restrict__ bet,
                                                  const int* __restrict__ batch,
                                                  const float* __restrict__ Wout,
                                                  int last) {
    int warp = threadIdx.x >> 5, lane = threadIdx.x & 31;
    int n = blockIdx.x * 8 + warp;
    if (n >= NN) return;

    const uint2* Mv = (const uint2*)g_m;   // 32 x uint2 per row (4 halves each)
    uint2* Hv = (uint2*)g_h;

    float dn = g_dis[n];
    float4 acc = make_float4(0.f, 0.f, 0.f, 0.f);
    fma_h4(acc, dn * dn, Mv[(size_t)n * 32 + lane]);   // self loop

    int beg = g_rowptr[n], end = g_rowptr[n + 1];
    int e = beg;
    for (; e + 4 <= end; e += 4) {
        uint2 c0 = g_cw[e],     c1 = g_cw[e + 1];
        uint2 c2 = g_cw[e + 2], c3 = g_cw[e + 3];
        uint2 u0 = Mv[(size_t)c0.x * 32 + lane];
        uint2 u1 = Mv[(size_t)c1.x * 32 + lane];
        uint2 u2 = Mv[(size_t)c2.x * 32 + lane];
        uint2 u3 = Mv[(size_t)c3.x * 32 + lane];
        fma_h4(acc, __uint_as_float(c0.y), u0);
        fma_h4(acc, __uint_as_float(c1.y), u1);
        fma_h4(acc, __uint_as_float(c2.y), u2);
        fma_h4(acc, __uint_as_float(c3.y), u3);
    }
    for (; e < end; e++) {
        uint2 cw = g_cw[e];
        fma_h4(acc, __uint_as_float(cw.y), Mv[(size_t)cw.x * 32 + lane]);
    }
    float4 bb = ((const float4*)b)[lane];
    acc.x += bb.x; acc.y += bb.y; acc.z += bb.z; acc.w += bb.w;

    float mu = warp_sum(acc.x + acc.y + acc.z + acc.w) * (1.f / 128.f);
    float4 dd = make_float4(acc.x - mu, acc.y - mu, acc.z - mu, acc.w - mu);
    float var = warp_sum(dd.x * dd.x + dd.y * dd.y + dd.z * dd.z + dd.w * dd.w) * (1.f / 128.f);
    float inv = rsqrtf(var + 1e-5f);

    float4 gg = ((const float4*)gam)[lane];
    float4 bt = ((const float4*)bet)[lane];
    float4 hv = h4_to_f4(Hv[(size_t)n * 32 + lane]);
    float4 o;
    o.x = fmaxf(dd.x * inv * gg.x + bt.x, 0.f) + hv.x;
    o.y = fmaxf(dd.y * inv * gg.y + bt.y, 0.f) + hv.y;
    o.z = fmaxf(dd.z * inv * gg.z + bt.z, 0.f) + hv.z;
    o.w = fmaxf(dd.w * inv * gg.w + bt.w, 0.f) + hv.w;

    if (!last) {
        Hv[(size_t)n * 32 + lane] = pack_h4(o);
    } else {
        // fused global-mean-pool contribution (h never re-read)
        float4 wv = ((const float4*)Wout)[lane];
        float p = warp_sum(o.x * wv.x + o.y * wv.y + o.z * wv.z + o.w * wv.w);
        if (lane == 0) {
            int gidx = batch[n];
            atomicAdd(&g_gsum[gidx], p);
            atomicAdd(&g_gcnt[gidx], 1.f);
        }
    }
}

__global__ void out_kernel(float* __restrict__ out, const float* __restrict__ bout) {
    int gidx = blockIdx.x * blockDim.x + threadIdx.x;
    if (gidx < GG)
        out[gidx] = g_gsum[gidx] / fmaxf(g_gcnt[gidx], 1.f) + bout[0];
}

// ---------------- launch ----------------
extern "C" void kernel_launch(void* const* d_in, const int* in_sizes, int n_in,
                              void* d_out, int out_size) {
    const float* x      = (const float*)d_in[0];
    const int*   eidx   = (const int*)d_in[1];    // int32 (JAX x64 disabled)
    const int*   batch  = (const int*)d_in[2];    // int32
    const float* Wemb   = (const float*)d_in[3];
    const float* bemb   = (const float*)d_in[4];
    const float* Wgnn   = (const float*)d_in[5];
    const float* bgnn   = (const float*)d_in[6];
    const float* gamma  = (const float*)d_in[7];
    const float* beta   = (const float*)d_in[8];
    const float* Wout   = (const float*)d_in[9];
    const float* bout   = (const float*)d_in[10];
    float* out = (float*)d_out;

    const int* src = eidx;
    const int* dst = eidx + EE;

    mega1_kernel<<<EMB_BLOCKS + ZERO_BLOCKS + PREP_BLOCKS, 256>>>(x, Wemb, bemb, Wgnn);
    count_kernel<<<(EE / 4 + 255) / 256, 256>>>(dst);
    scan_kernel<<<NB_SCAN, 1024>>>();
    fill_kernel<<<(EE / 4 + 255) / 256, 256>>>(src, dst);

    for (int l = 0; l < LL; l++) {
        gemm_mma_kernel<<<NT, 256>>>(l);
        agg_kernel<<<NN / 8, 256>>>(bgnn + l * HH, gamma + l * HH, beta + l * HH,
                                    batch, Wout, l == LL - 1);
    }

    out_kernel<<<(GG + 255) / 256, 256>>>(out, bout);
}

// round 16
// speedup vs baseline: 1.6447x; 1.0308x over previous
#include <cuda_runtime.h>
#include <cuda_fp16.h>
#include <cstdint>

#define NN 100000
#define EE 1600000
#define GG 4096
#define HH 128
#define LL 4
#define NT 782                  // ceil(100000/128) row-tiles of 128
#define NPAD (NT * 128)         // 100096
#define NB_SCAN 98              // ceil(NN/1024)

#define EMB_BLOCKS 12500        // NN/8
#define ZERO_BLOCKS 391         // ceil(NN/256)
#define PREP_BLOCKS 128

// ---------------- device scratch (no allocations allowed) ----------------
__device__ int     g_deg[NN];
__device__ int     g_rowptr[NN + 1];
__device__ int     g_rank[EE];               // within-row rank of each edge
__device__ uint2   g_cw[EE];                 // (src idx, weight bits) fused
__device__ float   g_dis[NN];
__device__ __align__(16) __half2 g_h[(size_t)NPAD * 64];   // N x 128 fp16 residual (zero-init)
__device__ __align__(16) __half2 g_m[(size_t)NPAD * 64];   // N x 128 fp16 (padded)
__device__ float   g_gsum[GG];
__device__ float   g_gcnt[GG];
// decoupled-lookback scan state
__device__ volatile int g_agg_[NB_SCAN];
__device__ volatile int g_incl_[NB_SCAN];
__device__ volatile int g_flag_[NB_SCAN];    // 0=none, 1=agg, 2=inclusive
// W in m16n8k16 fragment layout, fp16: [L][kc 8][nt 16][r 2][lane 32]
__device__ uint32_t g_Bfrag16[LL][8][16][2][32];

// ---------------- helpers ----------------
__device__ __forceinline__ uint32_t smem_u32(const void* p) {
    uint32_t a;
    asm("{ .reg .u64 t; cvta.to.shared.u64 t, %1; cvt.u32.u64 %0, t; }" : "=r"(a) : "l"(p));
    return a;
}
#define CP_ASYNC16(dst_u32, src_ptr) \
    asm volatile("cp.async.cg.shared.global [%0], [%1], 16;" :: "r"(dst_u32), "l"(src_ptr))
#define CP_COMMIT() asm volatile("cp.async.commit_group;")

__device__ __forceinline__ float warp_sum(float v) {
#pragma unroll
    for (int o = 16; o; o >>= 1) v += __shfl_xor_sync(0xffffffffu, v, o);
    return v;
}
__device__ __forceinline__ int warp_sum_i(int v) {
#pragma unroll
    for (int o = 16; o; o >>= 1) v += __shfl_xor_sync(0xffffffffu, v, o);
    return v;
}
__device__ __forceinline__ void fma4(float4& acc, float a, const float4& w) {
    acc.x = fmaf(a, w.x, acc.x);
    acc.y = fmaf(a, w.y, acc.y);
    acc.z = fmaf(a, w.z, acc.z);
    acc.w = fmaf(a, w.w, acc.w);
}
__device__ __forceinline__ void fma_h4(float4& acc, float w, uint2 u) {
    float2 f0 = __half22float2(*(__half2*)&u.x);
    float2 f1 = __half22float2(*(__half2*)&u.y);
    acc.x = fmaf(w, f0.x, acc.x);
    acc.y = fmaf(w, f0.y, acc.y);
    acc.z = fmaf(w, f1.x, acc.z);
    acc.w = fmaf(w, f1.y, acc.w);
}
__device__ __forceinline__ float4 h4_to_f4(uint2 u) {
    float2 f0 = __half22float2(*(__half2*)&u.x);
    float2 f1 = __half22float2(*(__half2*)&u.y);
    return make_float4(f0.x, f0.y, f1.x, f1.y);
}
__device__ __forceinline__ uint32_t pack_h2(float2 v) {
    __half2 h = __floats2half2_rn(v.x, v.y);
    return *(uint32_t*)&h;
}
__device__ __forceinline__ uint2 pack_h4(float4 v) {
    return make_uint2(pack_h2(make_float2(v.x, v.y)), pack_h2(make_float2(v.z, v.w)));
}
__device__ __forceinline__ void mma_f16(float* d, uint32_t a0, uint32_t a1,
                                        uint32_t a2, uint32_t a3,
                                        uint32_t b0, uint32_t b1) {
    asm("mma.sync.aligned.m16n8k16.row.col.f32.f16.f16.f32 "
        "{%0,%1,%2,%3},{%4,%5,%6,%7},{%8,%9},{%0,%1,%2,%3};"
        : "+f"(d[0]), "+f"(d[1]), "+f"(d[2]), "+f"(d[3])
        : "r"(a0), "r"(a1), "r"(a2), "r"(a3), "r"(b0), "r"(b1));
}

// ---------------- mega kernel 1: embed + zero + W prep (independent work) ------
__global__ void __launch_bounds__(256) mega1_kernel(const float* __restrict__ x,
                                                    const float* __restrict__ We,
                                                    const float* __restrict__ be,
                                                    const float* __restrict__ Wgnn) {
    int blk = blockIdx.x;
    int tid = threadIdx.x;
    if (blk < EMB_BLOCKS) {
        // ---- embed: h = relu(x @ W_embed + b_embed), fp16 out
        __shared__ __align__(16) float sW[11 * HH];
        for (int i = tid; i < 11 * HH; i += 256) sW[i] = We[i];
        __syncthreads();
        int warp = tid >> 5, lane = tid & 31;
        int n = blk * 8 + warp;
        if (n >= NN) return;
        float xv = (lane < 11) ? x[(size_t)n * 11 + lane] : 0.f;
        float4 acc = ((const float4*)be)[lane];
        const float4* sWv = (const float4*)sW;
#pragma unroll
        for (int k = 0; k < 11; k++) {
            float a = __shfl_sync(0xffffffffu, xv, k);
            fma4(acc, a, sWv[k * 32 + lane]);
        }
        acc.x = fmaxf(acc.x, 0.f); acc.y = fmaxf(acc.y, 0.f);
        acc.z = fmaxf(acc.z, 0.f); acc.w = fmaxf(acc.w, 0.f);
        ((uint2*)g_h)[(size_t)n * 32 + lane] = pack_h4(acc);
    } else if (blk < EMB_BLOCKS + ZERO_BLOCKS) {
        int i = (blk - EMB_BLOCKS) * 256 + tid;
        if (i < NN) g_deg[i] = 0;
        if (i < GG) { g_gsum[i] = 0.f; g_gcnt[i] = 0.f; }
        if (i < NB_SCAN) g_flag_[i] = 0;
    } else {
        // ---- W prep: fp16 into m16n8k16 fragment layout
        int idx = (blk - EMB_BLOCKS - ZERO_BLOCKS) * 256 + tid;
        if (idx >= LL * 8 * 16 * 2 * 32) return;
        int lane = idx & 31;
        int r    = (idx >> 5) & 1;
        int nt   = (idx >> 6) & 15;
        int kc   = (idx >> 10) & 7;
        int l    = idx >> 13;
        int t = lane & 3, g = lane >> 2;
        int k0 = kc * 16 + r * 8 + 2 * t;
        int n  = nt * 8 + g;
        float w0 = Wgnn[(size_t)l * 16384 + k0 * 128 + n];
        float w1 = Wgnn[(size_t)l * 16384 + (k0 + 1) * 128 + n];
        g_Bfrag16[l][kc][nt][r][lane] = pack_h2(make_float2(w0, w1));
    }
}

// ---------------- count: degree + per-edge rank (8 edges/thread) ---------------
__global__ void __launch_bounds__(256) count_kernel(const int* __restrict__ dst) {
    int e8 = (blockIdx.x * blockDim.x + threadIdx.x) * 8;
    if (e8 >= EE) return;
    int4 d0 = *(const int4*)(dst + e8);
    int4 d1 = *(const int4*)(dst + e8 + 4);
    int r0 = atomicAdd(&g_deg[d0.x], 1);
    int r1 = atomicAdd(&g_deg[d0.y], 1);
    int r2 = atomicAdd(&g_deg[d0.z], 1);
    int r3 = atomicAdd(&g_deg[d0.w], 1);
    int r4 = atomicAdd(&g_deg[d1.x], 1);
    int r5 = atomicAdd(&g_deg[d1.y], 1);
    int r6 = atomicAdd(&g_deg[d1.z], 1);
    int r7 = atomicAdd(&g_deg[d1.w], 1);
    *(int4*)(g_rank + e8)     = make_int4(r0, r1, r2, r3);
    *(int4*)(g_rank + e8 + 4) = make_int4(r4, r5, r6, r7);
}

// single-pass decoupled-lookback exclusive scan (+ dis); 98 blocks all resident
__global__ void __launch_bounds__(1024) scan_kernel() {
    __shared__ int sh[1024];
    __shared__ int s_prefix;
    int b = blockIdx.x, tid = threadIdx.x;
    int idx = b * 1024 + tid;
    int v = (idx < NN) ? g_deg[idx] : 0;
    if (idx < NN) g_dis[idx] = rsqrtf((float)(v + 1));   // +1 self loop
    sh[tid] = v;
    __syncthreads();
#pragma unroll
    for (int off = 1; off < 1024; off <<= 1) {
        int t = (tid >= off) ? sh[tid - off] : 0;
        __syncthreads();
        sh[tid] += t;
        __syncthreads();
    }
    int total = sh[1023];
    if (tid == 0) {
        g_agg_[b] = total;
        __threadfence();
        if (b == 0) {
            g_incl_[0] = total;
            __threadfence();
            g_flag_[0] = 2;
            s_prefix = 0;
        } else {
            g_flag_[b] = 1;
        }
    }
    if (b > 0 && tid < 32) {
        int prefix = 0;
        int i = b - 1;
        while (true) {
            int j = i - tid;
            int f = (j >= 0) ? g_flag_[j] : 2;
            while (__any_sync(0xffffffffu, (j >= 0) && f == 0))
                f = (j >= 0) ? g_flag_[j] : 2;
            unsigned mask2 = __ballot_sync(0xffffffffu, (j >= 0) && f == 2);
            int stop_lane = mask2 ? (__ffs(mask2) - 1) : 32;
            int contrib = 0;
            if (j >= 0 && tid <= stop_lane)
                contrib = (tid == stop_lane) ? g_incl_[j] : g_agg_[j];
            prefix += warp_sum_i((tid <= stop_lane) ? contrib : 0);
            if (stop_lane < 32) break;
            i -= 32;
        }
        if (tid == 0) {
            g_incl_[b] = prefix + total;
            __threadfence();
            g_flag_[b] = 2;
            s_prefix = prefix;
        }
    }
    __syncthreads();
    int prefix = s_prefix;
    if (idx < NN) g_rowptr[idx] = prefix + sh[tid] - v;  // exclusive
    if (b == NB_SCAN - 1 && tid == 0) g_rowptr[NN] = EE;
}

// ---------------- fill: atomic-free scatter (8 edges/thread) -------------------
__global__ void __launch_bounds__(256) fill_kernel(const int* __restrict__ src,
                                                   const int* __restrict__ dst) {
    int e8 = (blockIdx.x * blockDim.x + threadIdx.x) * 8;
    if (e8 >= EE) return;
#pragma unroll
    for (int q = 0; q < 2; q++) {
        int4 s = *(const int4*)(src + e8 + q * 4);
        int4 d = *(const int4*)(dst + e8 + q * 4);
        int4 r = *(const int4*)(g_rank + e8 + q * 4);
        float ds0 = g_dis[s.x], ds1 = g_dis[s.y], ds2 = g_dis[s.z], ds3 = g_dis[s.w];
        float dd0 = g_dis[d.x], dd1 = g_dis[d.y], dd2 = g_dis[d.z], dd3 = g_dis[d.w];
        int p0 = g_rowptr[d.x] + r.x;
        int p1 = g_rowptr[d.y] + r.y;
        int p2 = g_rowptr[d.z] + r.z;
        int p3 = g_rowptr[d.w] + r.w;
        g_cw[p0] = make_uint2((unsigned)s.x, __float_as_uint(ds0 * dd0));
        g_cw[p1] = make_uint2((unsigned)s.y, __float_as_uint(ds1 * dd1));
        g_cw[p2] = make_uint2((unsigned)s.z, __float_as_uint(ds2 * dd2));
        g_cw[p3] = make_uint2((unsigned)s.w, __float_as_uint(ds3 * dd3));
    }
}

// ---------------- mma.sync fp16 GEMM: g_m(half) = g_h(half) @ W(fp16) ---------
// Single-pass W; 3-stage cp.async ring, ONE syncthreads per K-chunk.
#define SA_STRIDE 12   // uints per row (8 + 4 pad)
__global__ void __launch_bounds__(256) gemm_mma_kernel(int layer) {
    __shared__ __align__(16) uint32_t sB[3][16][2][32];        // [buf][nt][r][lane] 12KB
    __shared__ __align__(16) uint32_t sA[3][128 * SA_STRIDE];  // 18KB

    int tid = threadIdx.x;
    int warp = tid >> 5, lane = tid & 31;
    int wm = warp >> 1;
    int wn = warp & 1;
    int g = lane >> 2, t = lane & 3;
    size_t rowbase = (size_t)blockIdx.x * 128;

    const char* hbase = (const char*)&g_h[rowbase * 64];   // 256 B per row
    const char* bsrc  = (const char*)&g_Bfrag16[layer][0][0][0][0];

    uint32_t sA_base = smem_u32(sA);
    uint32_t sB_base = smem_u32(sB);
    int r_ = tid >> 1, seg = tid & 1;

    float d[2][8][4];
#pragma unroll
    for (int mt = 0; mt < 2; mt++)
#pragma unroll
        for (int nt = 0; nt < 8; nt++)
#pragma unroll
            for (int j = 0; j < 4; j++) d[mt][nt][j] = 0.f;

    auto issue = [&](int c) {
        int buf = c % 3;
        uint32_t dstB = sB_base + buf * 4096 + tid * 16;
        const char* srcB = bsrc + (size_t)c * 4096 + tid * 16;
        CP_ASYNC16(dstB, srcB);
        uint32_t dstA = sA_base + buf * 6144 + (r_ * SA_STRIDE + seg * 4) * 4;
        const char* srcA = hbase + (size_t)r_ * 256 + c * 32 + seg * 16;
        CP_ASYNC16(dstA, srcA);
        CP_COMMIT();
    };

    issue(0);
    issue(1);
    for (int c = 0; c < 8; c++) {
        if (c < 7) asm volatile("cp.async.wait_group 1;");
        else       asm volatile("cp.async.wait_group 0;");
        __syncthreads();
        int buf = c % 3;

        uint32_t ah[2][4];
#pragma unroll
        for (int mt = 0; mt < 2; mt++) {
            int row = wm * 32 + mt * 16 + g;
            ah[mt][0] = sA[buf][row * SA_STRIDE + t];
            ah[mt][1] = sA[buf][(row + 8) * SA_STRIDE + t];
            ah[mt][2] = sA[buf][row * SA_STRIDE + 4 + t];
            ah[mt][3] = sA[buf][(row + 8) * SA_STRIDE + 4 + t];
        }
#pragma unroll
        for (int nt = 0; nt < 8; nt++) {
            int ntg = wn * 8 + nt;
            uint32_t b0 = sB[buf][ntg][0][lane];
            uint32_t b1 = sB[buf][ntg][1][lane];
#pragma unroll
            for (int mt = 0; mt < 2; mt++)
                mma_f16(d[mt][nt], ah[mt][0], ah[mt][1], ah[mt][2], ah[mt][3], b0, b1);
        }
        if (c + 2 < 8) issue(c + 2);
    }

#pragma unroll
    for (int mt = 0; mt < 2; mt++) {
        size_t row = rowbase + wm * 32 + mt * 16 + g;
#pragma unroll
        for (int nt = 0; nt < 8; nt++) {
            int colh = wn * 32 + nt * 4 + t;
            g_m[row * 64 + colh]       = __floats2half2_rn(d[mt][nt][0], d[mt][nt][1]);
            g_m[(row + 8) * 64 + colh] = __floats2half2_rn(d[mt][nt][2], d[mt][nt][3]);
        }
    }
}

// ------- fused aggregate + bias + LN + relu + residual (+ pool on last layer) ---
__global__ void __launch_bounds__(256) agg_kernel(const float* __restrict__ b,
                                                  const float* __restrict__ gam,
                                                  const float* __restrict__ bet,
                                                  const int* __restrict__ batch,
                                                  const float* __restrict__ Wout,
                                                  int last) {
    int warp = threadIdx.x >> 5, lane = threadIdx.x & 31;
    int n = blockIdx.x * 8 + warp;
    if (n >= NN) return;

    const uint2* Mv = (const uint2*)g_m;   // 32 x uint2 per row (4 halves each)
    uint2* Hv = (uint2*)g_h;

    float dn = g_dis[n];
    float4 acc = make_float4(0.f, 0.f, 0.f, 0.f);
    fma_h4(acc, dn * dn, Mv[(size_t)n * 32 + lane]);   // self loop

    int beg = g_rowptr[n], end = g_rowptr[n + 1];
    int e = beg;
    for (; e + 4 <= end; e += 4) {
        uint2 c0 = g_cw[e],     c1 = g_cw[e + 1];
        uint2 c2 = g_cw[e + 2], c3 = g_cw[e + 3];
        uint2 u0 = Mv[(size_t)c0.x * 32 + lane];
        uint2 u1 = Mv[(size_t)c1.x * 32 + lane];
        uint2 u2 = Mv[(size_t)c2.x * 32 + lane];
        uint2 u3 = Mv[(size_t)c3.x * 32 + lane];
        fma_h4(acc, __uint_as_float(c0.y), u0);
        fma_h4(acc, __uint_as_float(c1.y), u1);
        fma_h4(acc, __uint_as_float(c2.y), u2);
        fma_h4(acc, __uint_as_float(c3.y), u3);
    }
    for (; e < end; e++) {
        uint2 cw = g_cw[e];
        fma_h4(acc, __uint_as_float(cw.y), Mv[(size_t)cw.x * 32 + lane]);
    }
    float4 bb = ((const float4*)b)[lane];
    acc.x += bb.x; acc.y += bb.y; acc.z += bb.z; acc.w += bb.w;

    float mu = warp_sum(acc.x + acc.y + acc.z + acc.w) * (1.f / 128.f);
    float4 dd = make_float4(acc.x - mu, acc.y - mu, acc.z - mu, acc.w - mu);
    float var = warp_sum(dd.x * dd.x + dd.y * dd.y + dd.z * dd.z + dd.w * dd.w) * (1.f / 128.f);
    float inv = rsqrtf(var + 1e-5f);

    float4 gg = ((const float4*)gam)[lane];
    float4 bt = ((const float4*)bet)[lane];
    float4 hv = h4_to_f4(Hv[(size_t)n * 32 + lane]);
    float4 o;
    o.x = fmaxf(dd.x * inv * gg.x + bt.x, 0.f) + hv.x;
    o.y = fmaxf(dd.y * inv * gg.y + bt.y, 0.f) + hv.y;
    o.z = fmaxf(dd.z * inv * gg.z + bt.z, 0.f) + hv.z;
    o.w = fmaxf(dd.w * inv * gg.w + bt.w, 0.f) + hv.w;

    if (!last) {
        Hv[(size_t)n * 32 + lane] = pack_h4(o);
    } else {
        float4 wv = ((const float4*)Wout)[lane];
        float p = warp_sum(o.x * wv.x + o.y * wv.y + o.z * wv.z + o.w * wv.w);
        if (lane == 0) {
            int gidx = batch[n];
            atomicAdd(&g_gsum[gidx], p);
            atomicAdd(&g_gcnt[gidx], 1.f);
        }
    }
}

__global__ void out_kernel(float* __restrict__ out, const float* __restrict__ bout) {
    int gidx = blockIdx.x * blockDim.x + threadIdx.x;
    if (gidx < GG)
        out[gidx] = g_gsum[gidx] / fmaxf(g_gcnt[gidx], 1.f) + bout[0];
}

// ---------------- launch ----------------
extern "C" void kernel_launch(void* const* d_in, const int* in_sizes, int n_in,
                              void* d_out, int out_size) {
    const float* x      = (const float*)d_in[0];
    const int*   eidx   = (const int*)d_in[1];    // int32 (JAX x64 disabled)
    const int*   batch  = (const int*)d_in[2];    // int32
    const float* Wemb   = (const float*)d_in[3];
    const float* bemb   = (const float*)d_in[4];
    const float* Wgnn   = (const float*)d_in[5];
    const float* bgnn   = (const float*)d_in[6];
    const float* gamma  = (const float*)d_in[7];
    const float* beta   = (const float*)d_in[8];
    const float* Wout   = (const float*)d_in[9];
    const float* bout   = (const float*)d_in[10];
    float* out = (float*)d_out;

    const int* src = eidx;
    const int* dst = eidx + EE;

    mega1_kernel<<<EMB_BLOCKS + ZERO_BLOCKS + PREP_BLOCKS, 256>>>(x, Wemb, bemb, Wgnn);
    count_kernel<<<(EE / 8 + 255) / 256, 256>>>(dst);
    scan_kernel<<<NB_SCAN, 1024>>>();
    fill_kernel<<<(EE / 8 + 255) / 256, 256>>>(src, dst);

    for (int l = 0; l < LL; l++) {
        gemm_mma_kernel<<<NT, 256>>>(l);
        agg_kernel<<<NN / 8, 256>>>(bgnn + l * HH, gamma + l * HH, beta + l * HH,
                                    batch, Wout, l == LL - 1);
    }

    out_kernel<<<(GG + 255) / 256, 256>>>(out, bout);
}

// round 17
// speedup vs baseline: 1.7488x; 1.0633x over previous
#include <cuda_runtime.h>
#include <cuda_fp16.h>
#include <cstdint>

#define NN 100000
#define EE 1600000
#define GG 4096
#define HH 128
#define LL 4
#define NT 782                  // ceil(100000/128) row-tiles of 128
#define NPAD (NT * 128)         // 100096
#define NB_SCAN 98              // ceil(NN/1024)

#define EMB_BLOCKS 12500        // NN/8
#define ZERO_BLOCKS 391         // ceil(NN/256)
#define PREP_BLOCKS 128

// ---------------- device scratch (no allocations allowed) ----------------
__device__ int     g_deg[NN];
__device__ int     g_rowptr[NN + 1];
__device__ int     g_rank[EE];               // within-row rank of each edge
__device__ int     g_col[EE];                // CSR column (src) only — no weights
__device__ float   g_dis[NPAD];              // padded (GEMM epilogue reads < NPAD)
__device__ __align__(16) __half2 g_h[(size_t)NPAD * 64];   // N x 128 fp16 residual (zero-init)
__device__ __align__(16) __half2 g_m[(size_t)NPAD * 64];   // N x 128 fp16: m' = dis*m
__device__ float   g_gsum[GG];
__device__ float   g_gcnt[GG];
// decoupled-lookback scan state
__device__ volatile int g_agg_[NB_SCAN];
__device__ volatile int g_incl_[NB_SCAN];
__device__ volatile int g_flag_[NB_SCAN];    // 0=none, 1=agg, 2=inclusive
// W in m16n8k16 fragment layout, fp16: [L][kc 8][nt 16][r 2][lane 32]
__device__ uint32_t g_Bfrag16[LL][8][16][2][32];

// ---------------- helpers ----------------
__device__ __forceinline__ uint32_t smem_u32(const void* p) {
    uint32_t a;
    asm("{ .reg .u64 t; cvta.to.shared.u64 t, %1; cvt.u32.u64 %0, t; }" : "=r"(a) : "l"(p));
    return a;
}
#define CP_ASYNC16(dst_u32, src_ptr) \
    asm volatile("cp.async.cg.shared.global [%0], [%1], 16;" :: "r"(dst_u32), "l"(src_ptr))
#define CP_COMMIT() asm volatile("cp.async.commit_group;")

__device__ __forceinline__ float warp_sum(float v) {
#pragma unroll
    for (int o = 16; o; o >>= 1) v += __shfl_xor_sync(0xffffffffu, v, o);
    return v;
}
__device__ __forceinline__ int warp_sum_i(int v) {
#pragma unroll
    for (int o = 16; o; o >>= 1) v += __shfl_xor_sync(0xffffffffu, v, o);
    return v;
}
__device__ __forceinline__ void fma4(float4& acc, float a, const float4& w) {
    acc.x = fmaf(a, w.x, acc.x);
    acc.y = fmaf(a, w.y, acc.y);
    acc.z = fmaf(a, w.z, acc.z);
    acc.w = fmaf(a, w.w, acc.w);
}
__device__ __forceinline__ void add_h4(float4& acc, uint2 u) {
    float2 f0 = __half22float2(*(__half2*)&u.x);
    float2 f1 = __half22float2(*(__half2*)&u.y);
    acc.x += f0.x; acc.y += f0.y; acc.z += f1.x; acc.w += f1.y;
}
__device__ __forceinline__ float4 h4_to_f4(uint2 u) {
    float2 f0 = __half22float2(*(__half2*)&u.x);
    float2 f1 = __half22float2(*(__half2*)&u.y);
    return make_float4(f0.x, f0.y, f1.x, f1.y);
}
__device__ __forceinline__ uint32_t pack_h2(float2 v) {
    __half2 h = __floats2half2_rn(v.x, v.y);
    return *(uint32_t*)&h;
}
__device__ __forceinline__ uint2 pack_h4(float4 v) {
    return make_uint2(pack_h2(make_float2(v.x, v.y)), pack_h2(make_float2(v.z, v.w)));
}
__device__ __forceinline__ void mma_f16(float* d, uint32_t a0, uint32_t a1,
                                        uint32_t a2, uint32_t a3,
                                        uint32_t b0, uint32_t b1) {
    asm("mma.sync.aligned.m16n8k16.row.col.f32.f16.f16.f32 "
        "{%0,%1,%2,%3},{%4,%5,%6,%7},{%8,%9},{%0,%1,%2,%3};"
        : "+f"(d[0]), "+f"(d[1]), "+f"(d[2]), "+f"(d[3])
        : "r"(a0), "r"(a1), "r"(a2), "r"(a3), "r"(b0), "r"(b1));
}

// ---------------- mega kernel 1: embed + zero + W prep (independent work) ------
__global__ void __launch_bounds__(256) mega1_kernel(const float* __restrict__ x,
                                                    const float* __restrict__ We,
                                                    const float* __restrict__ be,
                                                    const float* __restrict__ Wgnn) {
    int blk = blockIdx.x;
    int tid = threadIdx.x;
    if (blk < EMB_BLOCKS) {
        // ---- embed: h = relu(x @ W_embed + b_embed), fp16 out
        __shared__ __align__(16) float sW[11 * HH];
        for (int i = tid; i < 11 * HH; i += 256) sW[i] = We[i];
        __syncthreads();
        int warp = tid >> 5, lane = tid & 31;
        int n = blk * 8 + warp;
        if (n >= NN) return;
        float xv = (lane < 11) ? x[(size_t)n * 11 + lane] : 0.f;
        float4 acc = ((const float4*)be)[lane];
        const float4* sWv = (const float4*)sW;
#pragma unroll
        for (int k = 0; k < 11; k++) {
            float a = __shfl_sync(0xffffffffu, xv, k);
            fma4(acc, a, sWv[k * 32 + lane]);
        }
        acc.x = fmaxf(acc.x, 0.f); acc.y = fmaxf(acc.y, 0.f);
        acc.z = fmaxf(acc.z, 0.f); acc.w = fmaxf(acc.w, 0.f);
        ((uint2*)g_h)[(size_t)n * 32 + lane] = pack_h4(acc);
    } else if (blk < EMB_BLOCKS + ZERO_BLOCKS) {
        int i = (blk - EMB_BLOCKS) * 256 + tid;
        if (i < NN) g_deg[i] = 0;
        if (i < GG) { g_gsum[i] = 0.f; g_gcnt[i] = 0.f; }
        if (i < NB_SCAN) g_flag_[i] = 0;
    } else {
        // ---- W prep: fp16 into m16n8k16 fragment layout
        int idx = (blk - EMB_BLOCKS - ZERO_BLOCKS) * 256 + tid;
        if (idx >= LL * 8 * 16 * 2 * 32) return;
        int lane = idx & 31;
        int r    = (idx >> 5) & 1;
        int nt   = (idx >> 6) & 15;
        int kc   = (idx >> 10) & 7;
        int l    = idx >> 13;
        int t = lane & 3, g = lane >> 2;
        int k0 = kc * 16 + r * 8 + 2 * t;
        int n  = nt * 8 + g;
        float w0 = Wgnn[(size_t)l * 16384 + k0 * 128 + n];
        float w1 = Wgnn[(size_t)l * 16384 + (k0 + 1) * 128 + n];
        g_Bfrag16[l][kc][nt][r][lane] = pack_h2(make_float2(w0, w1));
    }
}

// ---------------- count: degree + per-edge rank (4 edges/thread) ---------------
__global__ void __launch_bounds__(256) count_kernel(const int* __restrict__ dst) {
    int e4 = (blockIdx.x * blockDim.x + threadIdx.x) * 4;
    if (e4 >= EE) return;
    int4 d = *(const int4*)(dst + e4);
    int r0 = atomicAdd(&g_deg[d.x], 1);
    int r1 = atomicAdd(&g_deg[d.y], 1);
    int r2 = atomicAdd(&g_deg[d.z], 1);
    int r3 = atomicAdd(&g_deg[d.w], 1);
    *(int4*)(g_rank + e4) = make_int4(r0, r1, r2, r3);
}

// single-pass decoupled-lookback exclusive scan (+ dis); 98 blocks all resident
__global__ void __launch_bounds__(1024) scan_kernel() {
    __shared__ int sh[1024];
    __shared__ int s_prefix;
    int b = blockIdx.x, tid = threadIdx.x;
    int idx = b * 1024 + tid;
    int v = (idx < NN) ? g_deg[idx] : 0;
    if (idx < NPAD) g_dis[idx] = rsqrtf((float)(v + 1));   // +1 self loop (pad: 1.0)
    sh[tid] = v;
    __syncthreads();
#pragma unroll
    for (int off = 1; off < 1024; off <<= 1) {
        int t = (tid >= off) ? sh[tid - off] : 0;
        __syncthreads();
        sh[tid] += t;
        __syncthreads();
    }
    int total = sh[1023];
    if (tid == 0) {
        g_agg_[b] = total;
        __threadfence();
        if (b == 0) {
            g_incl_[0] = total;
            __threadfence();
            g_flag_[0] = 2;
            s_prefix = 0;
        } else {
            g_flag_[b] = 1;
        }
    }
    if (b > 0 && tid < 32) {
        int prefix = 0;
        int i = b - 1;
        while (true) {
            int j = i - tid;
            int f = (j >= 0) ? g_flag_[j] : 2;
            while (__any_sync(0xffffffffu, (j >= 0) && f == 0))
                f = (j >= 0) ? g_flag_[j] : 2;
            unsigned mask2 = __ballot_sync(0xffffffffu, (j >= 0) && f == 2);
            int stop_lane = mask2 ? (__ffs(mask2) - 1) : 32;
            int contrib = 0;
            if (j >= 0 && tid <= stop_lane)
                contrib = (tid == stop_lane) ? g_incl_[j] : g_agg_[j];
            prefix += warp_sum_i((tid <= stop_lane) ? contrib : 0);
            if (stop_lane < 32) break;
            i -= 32;
        }
        if (tid == 0) {
            g_incl_[b] = prefix + total;
            __threadfence();
            g_flag_[b] = 2;
            s_prefix = prefix;
        }
    }
    __syncthreads();
    int prefix = s_prefix;
    if (idx < NN) g_rowptr[idx] = prefix + sh[tid] - v;  // exclusive
    if (b == NB_SCAN - 1 && tid == 0) g_rowptr[NN] = EE;
}

// ---------------- fill: atomic-free col-only scatter (4 edges/thread) ----------
__global__ void __launch_bounds__(256) fill_kernel(const int* __restrict__ src,
                                                   const int* __restrict__ dst) {
    int e4 = (blockIdx.x * blockDim.x + threadIdx.x) * 4;
    if (e4 >= EE) return;
    int4 s = *(const int4*)(src + e4);
    int4 d = *(const int4*)(dst + e4);
    int4 r = *(const int4*)(g_rank + e4);
    g_col[g_rowptr[d.x] + r.x] = s.x;
    g_col[g_rowptr[d.y] + r.y] = s.y;
    g_col[g_rowptr[d.z] + r.z] = s.z;
    g_col[g_rowptr[d.w] + r.w] = s.w;
}

// ---------------- mma.sync fp16 GEMM: g_m(half) = dis * (g_h @ W) -------------
// Single-pass fp16 W; 3-stage cp.async ring; dis folded into epilogue.
#define SA_STRIDE 12   // uints per row (8 + 4 pad)
__global__ void __launch_bounds__(256) gemm_mma_kernel(int layer) {
    __shared__ __align__(16) uint32_t sB[3][16][2][32];        // [buf][nt][r][lane] 12KB
    __shared__ __align__(16) uint32_t sA[3][128 * SA_STRIDE];  // 18KB

    int tid = threadIdx.x;
    int warp = tid >> 5, lane = tid & 31;
    int wm = warp >> 1;
    int wn = warp & 1;
    int g = lane >> 2, t = lane & 3;
    size_t rowbase = (size_t)blockIdx.x * 128;

    const char* hbase = (const char*)&g_h[rowbase * 64];   // 256 B per row
    const char* bsrc  = (const char*)&g_Bfrag16[layer][0][0][0][0];

    uint32_t sA_base = smem_u32(sA);
    uint32_t sB_base = smem_u32(sB);
    int r_ = tid >> 1, seg = tid & 1;

    float d[2][8][4];
#pragma unroll
    for (int mt = 0; mt < 2; mt++)
#pragma unroll
        for (int nt = 0; nt < 8; nt++)
#pragma unroll
            for (int j = 0; j < 4; j++) d[mt][nt][j] = 0.f;

    auto issue = [&](int c) {
        int buf = c % 3;
        uint32_t dstB = sB_base + buf * 4096 + tid * 16;
        const char* srcB = bsrc + (size_t)c * 4096 + tid * 16;
        CP_ASYNC16(dstB, srcB);
        uint32_t dstA = sA_base + buf * 6144 + (r_ * SA_STRIDE + seg * 4) * 4;
        const char* srcA = hbase + (size_t)r_ * 256 + c * 32 + seg * 16;
        CP_ASYNC16(dstA, srcA);
        CP_COMMIT();
    };

    issue(0);
    issue(1);
    for (int c = 0; c < 8; c++) {
        if (c < 7) asm volatile("cp.async.wait_group 1;");
        else       asm volatile("cp.async.wait_group 0;");
        __syncthreads();
        int buf = c % 3;

        uint32_t ah[2][4];
#pragma unroll
        for (int mt = 0; mt < 2; mt++) {
            int row = wm * 32 + mt * 16 + g;
            ah[mt][0] = sA[buf][row * SA_STRIDE + t];
            ah[mt][1] = sA[buf][(row + 8) * SA_STRIDE + t];
            ah[mt][2] = sA[buf][row * SA_STRIDE + 4 + t];
            ah[mt][3] = sA[buf][(row + 8) * SA_STRIDE + 4 + t];
        }
#pragma unroll
        for (int nt = 0; nt < 8; nt++) {
            int ntg = wn * 8 + nt;
            uint32_t b0 = sB[buf][ntg][0][lane];
            uint32_t b1 = sB[buf][ntg][1][lane];
#pragma unroll
            for (int mt = 0; mt < 2; mt++)
                mma_f16(d[mt][nt], ah[mt][0], ah[mt][1], ah[mt][2], ah[mt][3], b0, b1);
        }
        if (c + 2 < 8) issue(c + 2);
    }

    // epilogue: m' = dis[row] * m, single fp16 rounding
#pragma unroll
    for (int mt = 0; mt < 2; mt++) {
        size_t row = rowbase + wm * 32 + mt * 16 + g;
        float dis0 = g_dis[row];
        float dis1 = g_dis[row + 8];
#pragma unroll
        for (int nt = 0; nt < 8; nt++) {
            int colh = wn * 32 + nt * 4 + t;
            g_m[row * 64 + colh]       = __floats2half2_rn(d[mt][nt][0] * dis0, d[mt][nt][1] * dis0);
            g_m[(row + 8) * 64 + colh] = __floats2half2_rn(d[mt][nt][2] * dis1, d[mt][nt][3] * dis1);
        }
    }
}

// ------- fused aggregate + bias + LN + relu + residual (+ pool on last layer) ---
__global__ void __launch_bounds__(256) agg_kernel(const float* __restrict__ b,
                                                  const float* __restrict__ gam,
                                                  const float* __restrict__ bet,
                                                  const int* __restrict__ batch,
                                                  const float* __restrict__ Wout,
                                                  int last) {
    int warp = threadIdx.x >> 5, lane = threadIdx.x & 31;
    int n = blockIdx.x * 8 + warp;
    if (n >= NN) return;

    const uint2* Mv = (const uint2*)g_m;   // 32 x uint2 per row (4 halves each)
    uint2* Hv = (uint2*)g_h;

    float dn = g_dis[n];
    float4 acc = h4_to_f4(Mv[(size_t)n * 32 + lane]);   // self loop: m'[n]

    int beg = g_rowptr[n], end = g_rowptr[n + 1];
    int e = beg;
    for (; e + 4 <= end; e += 4) {
        int c0 = g_col[e],     c1 = g_col[e + 1];
        int c2 = g_col[e + 2], c3 = g_col[e + 3];
        uint2 u0 = Mv[(size_t)c0 * 32 + lane];
        uint2 u1 = Mv[(size_t)c1 * 32 + lane];
        uint2 u2 = Mv[(size_t)c2 * 32 + lane];
        uint2 u3 = Mv[(size_t)c3 * 32 + lane];
        add_h4(acc, u0);
        add_h4(acc, u1);
        add_h4(acc, u2);
        add_h4(acc, u3);
    }
    for (; e < end; e++)
        add_h4(acc, Mv[(size_t)g_col[e] * 32 + lane]);

    // scale by dis[n], then bias
    float4 bb = ((const float4*)b)[lane];
    acc.x = fmaf(dn, acc.x, bb.x);
    acc.y = fmaf(dn, acc.y, bb.y);
    acc.z = fmaf(dn, acc.z, bb.z);
    acc.w = fmaf(dn, acc.w, bb.w);

    float mu = warp_sum(acc.x + acc.y + acc.z + acc.w) * (1.f / 128.f);
    float4 dd = make_float4(acc.x - mu, acc.y - mu, acc.z - mu, acc.w - mu);
    float var = warp_sum(dd.x * dd.x + dd.y * dd.y + dd.z * dd.z + dd.w * dd.w) * (1.f / 128.f);
    float inv = rsqrtf(var + 1e-5f);

    float4 gg = ((const float4*)gam)[lane];
    float4 bt = ((const float4*)bet)[lane];
    float4 hv = h4_to_f4(Hv[(size_t)n * 32 + lane]);
    float4 o;
    o.x = fmaxf(dd.x * inv * gg.x + bt.x, 0.f) + hv.x;
    o.y = fmaxf(dd.y * inv * gg.y + bt.y, 0.f) + hv.y;
    o.z = fmaxf(dd.z * inv * gg.z + bt.z, 0.f) + hv.z;
    o.w = fmaxf(dd.w * inv * gg.w + bt.w, 0.f) + hv.w;

    if (!last) {
        Hv[(size_t)n * 32 + lane] = pack_h4(o);
    } else {
        float4 wv = ((const float4*)Wout)[lane];
        float p = warp_sum(o.x * wv.x + o.y * wv.y + o.z * wv.z + o.w * wv.w);
        if (lane == 0) {
            int gidx = batch[n];
            atomicAdd(&g_gsum[gidx], p);
            atomicAdd(&g_gcnt[gidx], 1.f);
        }
    }
}

__global__ void out_kernel(float* __restrict__ out, const float* __restrict__ bout) {
    int gidx = blockIdx.x * blockDim.x + threadIdx.x;
    if (gidx < GG)
        out[gidx] = g_gsum[gidx] / fmaxf(g_gcnt[gidx], 1.f) + bout[0];
}

// ---------------- launch ----------------
extern "C" void kernel_launch(void* const* d_in, const int* in_sizes, int n_in,
                              void* d_out, int out_size) {
    const float* x      = (const float*)d_in[0];
    const int*   eidx   = (const int*)d_in[1];    // int32 (JAX x64 disabled)
    const int*   batch  = (const int*)d_in[2];    // int32
    const float* Wemb   = (const float*)d_in[3];
    const float* bemb   = (const float*)d_in[4];
    const float* Wgnn   = (const float*)d_in[5];
    const float* bgnn   = (const float*)d_in[6];
    const float* gamma  = (const float*)d_in[7];
    const float* beta   = (const float*)d_in[8];
    const float* Wout   = (const float*)d_in[9];
    const float* bout   = (const float*)d_in[10];
    float* out = (float*)d_out;

    const int* src = eidx;
    const int* dst = eidx + EE;

    mega1_kernel<<<EMB_BLOCKS + ZERO_BLOCKS + PREP_BLOCKS, 256>>>(x, Wemb, bemb, Wgnn);
    count_kernel<<<(EE / 4 + 255) / 256, 256>>>(dst);
    scan_kernel<<<NB_SCAN, 1024>>>();
    fill_kernel<<<(EE / 4 + 255) / 256, 256>>>(src, dst);

    for (int l = 0; l < LL; l++) {
        gemm_mma_kernel<<<NT, 256>>>(l);
        agg_kernel<<<NN / 8, 256>>>(bgnn + l * HH, gamma + l * HH, beta + l * HH,
                                    batch, Wout, l == LL - 1);
    }

    out_kernel<<<(GG + 255) / 256, 256>>>(out, bout);
}